// round 5
// baseline (speedup 1.0000x reference)
#include <cuda_runtime.h>
#include <cuda_bf16.h>
#include <math.h>
#include <stdint.h>

#define BATCH 32768
#define KP_X 832   // 784 padded to 26*32
#define KP_H 448   // 400 padded to 14*32

// ---------------- scratch (__device__ globals; no cudaMalloc allowed) ------
__device__ __align__(256) __nv_bfloat16 g_xhi[BATCH * KP_X];
__device__ __align__(256) __nv_bfloat16 g_xlo[BATCH * KP_X];
__device__ __align__(256) __nv_bfloat16 g_h1hi[BATCH * KP_H];
__device__ __align__(256) __nv_bfloat16 g_h1lo[BATCH * KP_H];
__device__ __align__(256) __nv_bfloat16 g_h3hi[BATCH * KP_H];
__device__ __align__(256) __nv_bfloat16 g_h3lo[BATCH * KP_H];
__device__ __align__(256) __nv_bfloat16 g_B1hi[400 * KP_X];
__device__ __align__(256) __nv_bfloat16 g_B1lo[400 * KP_X];
__device__ __align__(256) __nv_bfloat16 g_BQhi[2000 * KP_H];
__device__ __align__(256) __nv_bfloat16 g_BQlo[2000 * KP_H];
__device__ __align__(256) __nv_bfloat16 g_Bmehi[256 * KP_H];
__device__ __align__(256) __nv_bfloat16 g_Bmelo[256 * KP_H];
__device__ __align__(256) float g_bme[256];
__device__ __align__(256) __nv_bfloat16 g_B4hi[784 * KP_H];
__device__ __align__(256) __nv_bfloat16 g_B4lo[784 * KP_H];
__device__ float g_z[BATCH * 20];

// ---------------- helpers --------------------------------------------------
__device__ __forceinline__ uint32_t smem_u32(const void* p) {
    uint32_t a;
    asm("{ .reg .u64 t; cvta.to.shared.u64 t, %1; cvt.u32.u64 %0, t; }"
        : "=r"(a) : "l"(p));
    return a;
}
__device__ __forceinline__ void split2(float v, __nv_bfloat16& hi, __nv_bfloat16& lo) {
    hi = __float2bfloat16(v);
    lo = __float2bfloat16(v - __bfloat162float(hi));
}
template <int ACT>
__device__ __forceinline__ float act_apply(float v) {
    if (ACT == 1) return fmaxf(v, 0.f);
    if (ACT == 2) return expf(v);
    if (ACT == 3) return 1.f / (1.f + expf(-v));
    return v;
}

#define CP_ASYNC16(dst, src, sz) \
    asm volatile("cp.async.cg.shared.global [%0], [%1], 16, %2;" \
                 :: "r"(dst), "l"(src), "r"(sz) : "memory")
#define CP_COMMIT() asm volatile("cp.async.commit_group;" ::: "memory")
template <int NW>
__device__ __forceinline__ void cp_wait() {
    asm volatile("cp.async.wait_group %0;" :: "n"(NW) : "memory");
}

__device__ __forceinline__ void ldsm4(uint32_t* r, uint32_t addr) {
    asm volatile("ldmatrix.sync.aligned.m8n8.x4.shared.b16 {%0,%1,%2,%3}, [%4];"
                 : "=r"(r[0]), "=r"(r[1]), "=r"(r[2]), "=r"(r[3]) : "r"(addr));
}
__device__ __forceinline__ void mma16816(float* d, const uint32_t* a, const uint32_t* b) {
    asm volatile(
        "mma.sync.aligned.m16n8k16.row.col.f32.bf16.bf16.f32 "
        "{%0,%1,%2,%3}, {%4,%5,%6,%7}, {%8,%9}, {%0,%1,%2,%3};"
        : "+f"(d[0]), "+f"(d[1]), "+f"(d[2]), "+f"(d[3])
        : "r"(a[0]), "r"(a[1]), "r"(a[2]), "r"(a[3]), "r"(b[0]), "r"(b[1]));
}

// Row stride 64B (32 bf16); XOR-swizzle 16B chunks: chunkpos = chunk ^ ((row>>1)&3)
__device__ __forceinline__ uint32_t swoff(int row, int chunk) {
    return ((uint32_t)row << 6) + ((uint32_t)((chunk ^ ((row >> 1) & 3))) << 4);
}

// ---------------- split kernels -------------------------------------------
__global__ void split_a4(const float* __restrict__ A, __nv_bfloat16* __restrict__ hi,
                         __nv_bfloat16* __restrict__ lo) {
    const int per_row = KP_X / 4;  // 208
    long i = (long)blockIdx.x * blockDim.x + threadIdx.x;
    if (i >= (long)BATCH * per_row) return;
    int k4 = (int)(i % per_row);
    long r = i / per_row;
    int k = k4 * 4;
    float4 v = make_float4(0.f, 0.f, 0.f, 0.f);
    if (k < 784) v = *(const float4*)(A + r * 784 + k);
    __nv_bfloat16 h[4], l[4];
    split2(v.x, h[0], l[0]);
    split2(v.y, h[1], l[1]);
    split2(v.z, h[2], l[2]);
    split2(v.w, h[3], l[3]);
    *(uint2*)(hi + r * KP_X + k) = *(uint2*)h;
    *(uint2*)(lo + r * KP_X + k) = *(uint2*)l;
}

// W [K,N] fp32 -> out [Np,Kp] bf16 (transposed, padded), smem-tiled transpose
__global__ void __launch_bounds__(256)
split_wt(const float* __restrict__ W, __nv_bfloat16* __restrict__ hi,
         __nv_bfloat16* __restrict__ lo, int K, int N, int Kp, int Np) {
    __shared__ float s[32][33];
    const int tx = threadIdx.x & 31, ty = threadIdx.x >> 5;  // 32x8
    const int tileN = blockIdx.x * 32, tileK = blockIdx.y * 32;
#pragma unroll
    for (int r = 0; r < 4; r++) {
        int kk = tileK + ty + r * 8, nn = tileN + tx;
        s[ty + r * 8][tx] = (kk < K && nn < N) ? W[(size_t)kk * N + nn] : 0.f;
    }
    __syncthreads();
#pragma unroll
    for (int r = 0; r < 4; r++) {
        int nn = tileN + ty + r * 8, kk = tileK + tx;
        if (nn < Np && kk < Kp) {
            __nv_bfloat16 h, l;
            split2(s[tx][ty + r * 8], h, l);
            hi[(size_t)nn * Kp + kk] = h;
            lo[(size_t)nn * Kp + kk] = l;
        }
    }
}

// Build fused mu|eigen weight buffer [256,KP_H] + combined bias [256]
__global__ void prep_me(const float* __restrict__ Wmu, const float* __restrict__ bmu,
                        const float* __restrict__ We, const float* __restrict__ be,
                        __nv_bfloat16* __restrict__ hi, __nv_bfloat16* __restrict__ lo,
                        float* __restrict__ bias) {
    int i = blockIdx.x * blockDim.x + threadIdx.x;
    if (i < 256) {
        bias[i] = (i < 100) ? bmu[i] : ((i >= 128 && i < 228) ? be[i - 128] : 0.f);
    }
    if (i >= 256 * KP_H) return;
    int n = i / KP_H, k = i % KP_H;
    float v = 0.f;
    if (k < 400) {
        if (n < 100) v = Wmu[(size_t)k * 100 + n];
        else if (n >= 128 && n < 228) v = We[(size_t)k * 100 + (n - 128)];
    }
    __nv_bfloat16 h, l;
    split2(v, h, l);
    hi[i] = h;
    lo[i] = l;
}

// ---------------- 3-term bf16 split GEMM on mma.sync -----------------------
// C[M,N] = act((Ahi+Alo)[M,Kp] @ ((Bhi+Blo)[N,Kp])^T + bias)
// 128x128x32 CTA tile, 8 warps (4x2), warp tile 32x64, 3-stage cp.async.
// Mainloop: load ALL fragments per kk, then 3 phases of 16 independent MMAs
// (hi*hi, lo*hi, hi*lo) so accumulator reuse distance covers HMMA latency.
#define STAGES 3
#define STAGE_BYTES 32768
#define GEMM_SMEM (STAGES * STAGE_BYTES)

template <int ACT, bool SPLIT_OUT>
__global__ void __launch_bounds__(256)
mma_gemm(const __nv_bfloat16* __restrict__ Ahi, const __nv_bfloat16* __restrict__ Alo,
         const __nv_bfloat16* __restrict__ Bhi, const __nv_bfloat16* __restrict__ Blo,
         const float* __restrict__ bias, float* __restrict__ C, float* __restrict__ C2,
         __nv_bfloat16* __restrict__ outHi, __nv_bfloat16* __restrict__ outLo,
         int N, int Kp, int ldOut) {
    extern __shared__ char smem[];
    const uint32_t sbase = smem_u32(smem);
    const int tid = threadIdx.x, wid = tid >> 5, lane = tid & 31;
    const int wm = wid >> 1, wn = wid & 1;
    const int rowBase = blockIdx.y * 128, colBase = blockIdx.x * 128;
    const int NC = Kp >> 5;

    float acc[2][8][4];
#pragma unroll
    for (int i = 0; i < 2; i++)
#pragma unroll
        for (int j = 0; j < 8; j++)
#pragma unroll
            for (int q = 0; q < 4; q++) acc[i][j][q] = 0.f;

    auto load_stage = [&](int c, int stg) {
        const int kBase = c << 5;
        const uint32_t sb = sbase + stg * STAGE_BYTES;
#pragma unroll
        for (int t = 0; t < 4; t++) {
            const __nv_bfloat16* P = (t == 0) ? Ahi : (t == 1) ? Alo
                                   : (t == 2) ? Bhi : Blo;
            const bool isB = (t >= 2);
#pragma unroll
            for (int i = 0; i < 2; i++) {
                int cid = tid + i * 256;          // 0..511
                int row = cid >> 2, ch = cid & 3;
                uint32_t dst = sb + t * 8192 + swoff(row, ch);
                int gr, sz = 16;
                if (isB) {
                    gr = colBase + row;
                    if (gr >= N) { gr = 0; sz = 0; }
                } else {
                    gr = rowBase + row;
                }
                const void* src = P + (size_t)gr * Kp + kBase + ch * 8;
                CP_ASYNC16(dst, src, sz);
            }
        }
    };

    load_stage(0, 0);
    CP_COMMIT();
    load_stage(1, 1);
    CP_COMMIT();

    for (int c = 0; c < NC; c++) {
        cp_wait<STAGES - 2>();
        __syncthreads();
        if (c + STAGES - 1 < NC) {
            load_stage(c + STAGES - 1, (c + STAGES - 1) % STAGES);
            CP_COMMIT();
        }
        const uint32_t sb = sbase + (c % STAGES) * STAGE_BYTES;
#pragma unroll
        for (int kk = 0; kk < 2; kk++) {
            uint32_t ahi[2][4], alo[2][4], bhi[4][4], blo[4][4];
            // ---- load all fragments for this kk ----
#pragma unroll
            for (int mi = 0; mi < 2; mi++) {
                int row = wm * 32 + mi * 16 + (lane & 15);
                int ch = kk * 2 + (lane >> 4);
                uint32_t o = swoff(row, ch);
                ldsm4(ahi[mi], sb + o);
                ldsm4(alo[mi], sb + 8192 + o);
            }
#pragma unroll
            for (int bi = 0; bi < 4; bi++) {
                int row = wn * 64 + bi * 16 + (lane & 7) + ((lane >> 4) << 3);
                int ch = kk * 2 + ((lane >> 3) & 1);
                uint32_t o = swoff(row, ch);
                ldsm4(bhi[bi], sb + 16384 + o);
                ldsm4(blo[bi], sb + 24576 + o);
            }
            // ---- phase 1: hi * hi (16 independent MMAs) ----
#pragma unroll
            for (int bi = 0; bi < 4; bi++)
#pragma unroll
                for (int mi = 0; mi < 2; mi++) {
                    mma16816(acc[mi][2 * bi],     ahi[mi], bhi[bi]);
                    mma16816(acc[mi][2 * bi + 1], ahi[mi], bhi[bi] + 2);
                }
            // ---- phase 2: lo * hi ----
#pragma unroll
            for (int bi = 0; bi < 4; bi++)
#pragma unroll
                for (int mi = 0; mi < 2; mi++) {
                    mma16816(acc[mi][2 * bi],     alo[mi], bhi[bi]);
                    mma16816(acc[mi][2 * bi + 1], alo[mi], bhi[bi] + 2);
                }
            // ---- phase 3: hi * lo ----
#pragma unroll
            for (int bi = 0; bi < 4; bi++)
#pragma unroll
                for (int mi = 0; mi < 2; mi++) {
                    mma16816(acc[mi][2 * bi],     ahi[mi], blo[bi]);
                    mma16816(acc[mi][2 * bi + 1], ahi[mi], blo[bi] + 2);
                }
        }
    }

    // ---------------- epilogue ----------------
#pragma unroll
    for (int mi = 0; mi < 2; mi++) {
#pragma unroll
        for (int ni = 0; ni < 8; ni++) {
            const float* a4 = acc[mi][ni];
            const int r0 = rowBase + wm * 32 + mi * 16 + (lane >> 2);
            const int col = colBase + wn * 64 + ni * 8 + ((lane & 3) << 1);
            float b0 = (col < N) ? bias[col] : 0.f;
            float b1 = (col + 1 < N) ? bias[col + 1] : 0.f;
#pragma unroll
            for (int h = 0; h < 2; h++) {
                const size_t row = (size_t)(r0 + h * 8);
                if (ACT == 4) {
                    float v0 = a4[2 * h + 0] + b0;
                    float v1 = a4[2 * h + 1] + b1;
                    if (col < 100) C[row * 100 + col] = v0;
                    else if (col >= 128 && col < 228) C2[row * 100 + col - 128] = expf(v0);
                    if (col + 1 < 100) C[row * 100 + col + 1] = v1;
                    else if (col + 1 >= 128 && col + 1 < 228) C2[row * 100 + col + 1 - 128] = expf(v1);
                    continue;
                }
                const float v0 = act_apply<ACT>(a4[2 * h + 0] + b0);
                const float v1 = act_apply<ACT>(a4[2 * h + 1] + b1);
                if (SPLIT_OUT) {
                    if (col < N) {
                        __nv_bfloat16 hh, ll;
                        split2(v0, hh, ll);
                        outHi[row * ldOut + col] = hh;
                        outLo[row * ldOut + col] = ll;
                        if (col + 1 < N) {
                            split2(v1, hh, ll);
                            outHi[row * ldOut + col + 1] = hh;
                            outLo[row * ldOut + col + 1] = ll;
                        } else if (col + 1 < ldOut) {
                            outHi[row * ldOut + col + 1] = __float2bfloat16(0.f);
                            outLo[row * ldOut + col + 1] = __float2bfloat16(0.f);
                        }
                    } else if (col < ldOut) {
                        outHi[row * ldOut + col] = __float2bfloat16(0.f);
                        outLo[row * ldOut + col] = __float2bfloat16(0.f);
                        if (col + 1 < ldOut) {
                            outHi[row * ldOut + col + 1] = __float2bfloat16(0.f);
                            outLo[row * ldOut + col + 1] = __float2bfloat16(0.f);
                        }
                    }
                } else {
                    if (col < N) C[row * ldOut + col] = v0;
                    if (col + 1 < N) C[row * ldOut + col + 1] = v1;
                }
            }
        }
    }
}

// ---------------- per-row solve kernel ------------------------------------
__global__ void __launch_bounds__(256)
solve_kernel(const float* __restrict__ Wa, const float* __restrict__ ba,
             const float* __restrict__ u, const float* __restrict__ eps,
             const __nv_bfloat16* __restrict__ h1hi, const __nv_bfloat16* __restrict__ h1lo,
             const float* __restrict__ outQ, const float* __restrict__ outMu,
             const float* __restrict__ outEig, float* __restrict__ outA,
             float* __restrict__ z) {
    __shared__ float Qs[8][400];
    const unsigned FULL = 0xffffffffu;
    const int w = threadIdx.x >> 5, lane = threadIdx.x & 31;
    const int row = blockIdx.x * 8 + w;

    float s0 = 0, s1 = 0, s2 = 0, s3 = 0, s4 = 0;
    const __nv_bfloat16* hh = h1hi + (size_t)row * KP_H;
    const __nv_bfloat16* hl = h1lo + (size_t)row * KP_H;
    for (int k = lane; k < 400; k += 32) {
        float h = __bfloat162float(hh[k]) + __bfloat162float(hl[k]);
        const float* wk = Wa + k * 5;
        s0 = fmaf(h, wk[0], s0);
        s1 = fmaf(h, wk[1], s1);
        s2 = fmaf(h, wk[2], s2);
        s3 = fmaf(h, wk[3], s3);
        s4 = fmaf(h, wk[4], s4);
    }
#pragma unroll
    for (int off = 16; off; off >>= 1) {
        s0 += __shfl_xor_sync(FULL, s0, off);
        s1 += __shfl_xor_sync(FULL, s1, off);
        s2 += __shfl_xor_sync(FULL, s2, off);
        s3 += __shfl_xor_sync(FULL, s3, off);
        s4 += __shfl_xor_sync(FULL, s4, off);
    }
    s0 += ba[0]; s1 += ba[1]; s2 += ba[2]; s3 += ba[3]; s4 += ba[4];
    float mx = fmaxf(fmaxf(fmaxf(s0, s1), fmaxf(s2, s3)), s4);
    float e0 = expf(s0 - mx), e1 = expf(s1 - mx), e2 = expf(s2 - mx),
          e3 = expf(s3 - mx), e4 = expf(s4 - mx);
    float inv = 1.f / (e0 + e1 + e2 + e3 + e4);
    float av[5] = {e0 * inv, e1 * inv, e2 * inv, e3 * inv, e4 * inv};
    if (lane == 0) {
        float* ar = outA + (size_t)row * 5;
        ar[0] = av[0]; ar[1] = av[1]; ar[2] = av[2]; ar[3] = av[3]; ar[4] = av[4];
    }

    float uu = u[row];
    int idx = 0;
    bool found = false;
    float c = 0.f;
#pragma unroll
    for (int j = 0; j < 5; j++) {
        c += av[j];
        if (!found && uu < c) { idx = j; found = true; }
    }

    const float* Qr = outQ + (size_t)row * 2000 + idx * 400;
    for (int k = lane; k < 400; k += 32) Qs[w][k] = Qr[k];
    __syncwarp();

    float o[20], r[20];
    float rhs = 0.f, eig = 0.f, mui = 0.f;
    if (lane < 20) {
#pragma unroll
        for (int j = 0; j < 20; j++) o[j] = Qs[w][lane * 20 + j];
        rhs = eps[(size_t)row * 20 + lane];
        eig = outEig[(size_t)row * 100 + idx * 20 + lane];
        mui = outMu[(size_t)row * 100 + idx * 20 + lane];
    } else {
#pragma unroll
        for (int j = 0; j < 20; j++) o[j] = 0.f;
    }
#pragma unroll
    for (int j = 0; j < 20; j++) r[j] = o[j];

#pragma unroll
    for (int k = 0; k < 20; k++) {
        float key = (lane >= k && lane < 20) ? fabsf(r[k]) : -1.0f;
        int pi = lane;
#pragma unroll
        for (int off = 16; off; off >>= 1) {
            float ok = __shfl_xor_sync(FULL, key, off);
            int oi = __shfl_xor_sync(FULL, pi, off);
            if (ok > key || (ok == key && oi < pi)) { key = ok; pi = oi; }
        }
        if (pi != k) {
            int partner = (lane == k) ? pi : ((lane == pi) ? k : lane);
#pragma unroll
            for (int j = 0; j < 20; j++) r[j] = __shfl_sync(FULL, r[j], partner);
            rhs = __shfl_sync(FULL, rhs, partner);
        }
        float akk = __shfl_sync(FULL, r[k], k);
        float m = (lane > k && lane < 20) ? r[k] / akk : 0.0f;
        float rk = __shfl_sync(FULL, rhs, k);
        rhs = fmaf(-m, rk, rhs);
#pragma unroll
        for (int j = k + 1; j < 20; j++) {
            float akj = __shfl_sync(FULL, r[j], k);
            r[j] = fmaf(-m, akj, r[j]);
        }
    }

    float y = 0.f;
#pragma unroll
    for (int k = 19; k >= 0; k--) {
        float num = __shfl_sync(FULL, rhs, k);
        float akk = __shfl_sync(FULL, r[k], k);
        float yk = num / akk;
        if (lane == k) y = yk;
        if (lane < k) rhs = fmaf(-r[k], yk, rhs);
    }

    float wv = eig * y;
    float zv = mui;
#pragma unroll
    for (int j = 0; j < 20; j++) {
        float wj = __shfl_sync(FULL, wv, j);
        zv = fmaf(o[j], wj, zv);
    }
    if (lane < 20) z[(size_t)row * 20 + lane] = zv;
}

// ---------------- h3 = relu(z@W3+b3) -> bf16 hi/lo (pads cols 400..447) ---
__global__ void __launch_bounds__(128)
h3_kernel(const float* __restrict__ z, const float* __restrict__ W3,
          const float* __restrict__ b3, __nv_bfloat16* __restrict__ h3hi,
          __nv_bfloat16* __restrict__ h3lo) {
    __shared__ float zs[32 * 20];
    const int col = blockIdx.x * 128 + threadIdx.x;
    const int row0 = blockIdx.y * 32;
    for (int i = threadIdx.x; i < 32 * 20; i += 128)
        zs[i] = z[(size_t)row0 * 20 + i];
    __syncthreads();

    if (col < KP_H) {
        if (col < 400) {
            float wcol[20];
#pragma unroll
            for (int k = 0; k < 20; k++) wcol[k] = W3[k * 400 + col];
            float bias = b3[col];
            for (int rr = 0; rr < 32; rr++) {
                float acc = bias;
#pragma unroll
                for (int k = 0; k < 20; k++)
                    acc = fmaf(zs[rr * 20 + k], wcol[k], acc);
                float v = fmaxf(acc, 0.f);
                __nv_bfloat16 h, l;
                split2(v, h, l);
                h3hi[(size_t)(row0 + rr) * KP_H + col] = h;
                h3lo[(size_t)(row0 + rr) * KP_H + col] = l;
            }
        } else {
            for (int rr = 0; rr < 32; rr++) {
                h3hi[(size_t)(row0 + rr) * KP_H + col] = __float2bfloat16(0.f);
                h3lo[(size_t)(row0 + rr) * KP_H + col] = __float2bfloat16(0.f);
            }
        }
    }
}

// ---------------- launch ---------------------------------------------------
extern "C" void kernel_launch(void* const* d_in, const int* in_sizes, int n_in,
                              void* d_out, int out_size) {
    const float* x   = (const float*)d_in[0];
    const float* u   = (const float*)d_in[1];
    const float* eps = (const float*)d_in[2];
    const float* W1  = (const float*)d_in[3];
    const float* b1  = (const float*)d_in[4];
    const float* Wmu = (const float*)d_in[5];
    const float* bmu = (const float*)d_in[6];
    const float* WQ  = (const float*)d_in[7];
    const float* bQ  = (const float*)d_in[8];
    const float* Wa  = (const float*)d_in[9];
    const float* ba  = (const float*)d_in[10];
    const float* We  = (const float*)d_in[11];
    const float* be  = (const float*)d_in[12];
    const float* W3  = (const float*)d_in[13];
    const float* b3  = (const float*)d_in[14];
    const float* W4  = (const float*)d_in[15];
    const float* b4  = (const float*)d_in[16];

    float* out = (float*)d_out;
    float* out_recon = out;
    float* out_mu    = out_recon + (size_t)BATCH * 784;
    float* out_Q     = out_mu    + (size_t)BATCH * 100;
    float* out_a     = out_Q     + (size_t)BATCH * 2000;
    float* out_eig   = out_a     + (size_t)BATCH * 5;

    __nv_bfloat16 *xhi, *xlo, *h1hi, *h1lo, *h3hi, *h3lo;
    __nv_bfloat16 *B1hi, *B1lo, *BQhi, *BQlo, *Bmehi, *Bmelo, *B4hi, *B4lo;
    float *zp, *bme;
    cudaGetSymbolAddress((void**)&xhi, g_xhi);
    cudaGetSymbolAddress((void**)&xlo, g_xlo);
    cudaGetSymbolAddress((void**)&h1hi, g_h1hi);
    cudaGetSymbolAddress((void**)&h1lo, g_h1lo);
    cudaGetSymbolAddress((void**)&h3hi, g_h3hi);
    cudaGetSymbolAddress((void**)&h3lo, g_h3lo);
    cudaGetSymbolAddress((void**)&B1hi, g_B1hi);
    cudaGetSymbolAddress((void**)&B1lo, g_B1lo);
    cudaGetSymbolAddress((void**)&BQhi, g_BQhi);
    cudaGetSymbolAddress((void**)&BQlo, g_BQlo);
    cudaGetSymbolAddress((void**)&Bmehi, g_Bmehi);
    cudaGetSymbolAddress((void**)&Bmelo, g_Bmelo);
    cudaGetSymbolAddress((void**)&bme, g_bme);
    cudaGetSymbolAddress((void**)&B4hi, g_B4hi);
    cudaGetSymbolAddress((void**)&B4lo, g_B4lo);
    cudaGetSymbolAddress((void**)&zp, g_z);

    cudaFuncSetAttribute(mma_gemm<1, true>,  cudaFuncAttributeMaxDynamicSharedMemorySize, GEMM_SMEM);
    cudaFuncSetAttribute(mma_gemm<2, false>, cudaFuncAttributeMaxDynamicSharedMemorySize, GEMM_SMEM);
    cudaFuncSetAttribute(mma_gemm<4, false>, cudaFuncAttributeMaxDynamicSharedMemorySize, GEMM_SMEM);
    cudaFuncSetAttribute(mma_gemm<3, false>, cudaFuncAttributeMaxDynamicSharedMemorySize, GEMM_SMEM);

    // #1 x split (vectorized)
    {
        long tot = (long)BATCH * (KP_X / 4);
        split_a4<<<(unsigned)((tot + 255) / 256), 256>>>(x, xhi, xlo);
    }
    // #2 W1 split (tiled transpose)
    split_wt<<<dim3((400 + 31) / 32, (KP_X + 31) / 32), 256>>>(W1, B1hi, B1lo, 784, 400, KP_X, 400);
    // #3 WQ split
    split_wt<<<dim3((2000 + 31) / 32, (KP_H + 31) / 32), 256>>>(WQ, BQhi, BQlo, 400, 2000, KP_H, 2000);
    // #4 fused mu|eigen weight + bias prep
    prep_me<<<(256 * KP_H + 255) / 256, 256>>>(Wmu, bmu, We, be, Bmehi, Bmelo, bme);
    // #5 h1 = relu(x@W1+b1) -> bf16 hi/lo
    mma_gemm<1, true><<<dim3(4, 256), 256, GEMM_SMEM>>>(
        xhi, xlo, B1hi, B1lo, b1, nullptr, nullptr, h1hi, h1lo, 400, KP_X, KP_H);
    // #6 Q = exp(h1@WQ+bQ)
    mma_gemm<2, false><<<dim3(16, 256), 256, GEMM_SMEM>>>(
        h1hi, h1lo, BQhi, BQlo, bQ, out_Q, nullptr, nullptr, nullptr, 2000, KP_H, 2000);
    // #7 W4 split
    split_wt<<<dim3((784 + 31) / 32, (KP_H + 31) / 32), 256>>>(W4, B4hi, B4lo, 400, 784, KP_H, 784);
    // #8 fused mu + eigen GEMM (N=256)
    mma_gemm<4, false><<<dim3(2, 256), 256, GEMM_SMEM>>>(
        h1hi, h1lo, Bmehi, Bmelo, bme, out_mu, out_eig, nullptr, nullptr, 256, KP_H, 100);
    // #9 softmax / idx / LU solve / z
    solve_kernel<<<BATCH / 8, 256>>>(Wa, ba, u, eps, h1hi, h1lo, out_Q, out_mu,
                                     out_eig, out_a, zp);
    // #10 h3 = relu(z@W3+b3) -> bf16 hi/lo
    h3_kernel<<<dim3(4, BATCH / 32), 128>>>(zp, W3, b3, h3hi, h3lo);
    // #11 recon = sigmoid(h3@W4+b4)
    mma_gemm<3, false><<<dim3(7, 256), 256, GEMM_SMEM>>>(
        h3hi, h3lo, B4hi, B4lo, b4, out_recon, nullptr, nullptr, nullptr, 784, KP_H, 784);
}

// round 6
// speedup vs baseline: 1.2136x; 1.2136x over previous
#include <cuda_runtime.h>
#include <cuda_bf16.h>
#include <math.h>
#include <stdint.h>

#define BATCH 32768
#define KP_X 832   // 784 padded to 26*32
#define KP_H 448   // 400 padded to 14*32

// ---------------- scratch (__device__ globals; no cudaMalloc allowed) ------
__device__ __align__(256) __nv_bfloat16 g_xhi[BATCH * KP_X];
__device__ __align__(256) __nv_bfloat16 g_xlo[BATCH * KP_X];
__device__ __align__(256) __nv_bfloat16 g_h1hi[BATCH * KP_H];
__device__ __align__(256) __nv_bfloat16 g_h1lo[BATCH * KP_H];
__device__ __align__(256) __nv_bfloat16 g_h3hi[BATCH * KP_H];
__device__ __align__(256) __nv_bfloat16 g_h3lo[BATCH * KP_H];
__device__ __align__(256) __nv_bfloat16 g_B1hi[400 * KP_X];
__device__ __align__(256) __nv_bfloat16 g_B1lo[400 * KP_X];
__device__ __align__(256) __nv_bfloat16 g_BQhi[2000 * KP_H];
__device__ __align__(256) __nv_bfloat16 g_BQlo[2000 * KP_H];
__device__ __align__(256) __nv_bfloat16 g_Bmehi[256 * KP_H];
__device__ __align__(256) __nv_bfloat16 g_Bmelo[256 * KP_H];
__device__ __align__(256) float g_bme[256];
__device__ __align__(256) __nv_bfloat16 g_B4hi[784 * KP_H];
__device__ __align__(256) __nv_bfloat16 g_B4lo[784 * KP_H];
__device__ float g_z[BATCH * 20];

// ---------------- helpers --------------------------------------------------
__device__ __forceinline__ uint32_t smem_u32(const void* p) {
    uint32_t a;
    asm("{ .reg .u64 t; cvta.to.shared.u64 t, %1; cvt.u32.u64 %0, t; }"
        : "=r"(a) : "l"(p));
    return a;
}
__device__ __forceinline__ void split2(float v, __nv_bfloat16& hi, __nv_bfloat16& lo) {
    hi = __float2bfloat16(v);
    lo = __float2bfloat16(v - __bfloat162float(hi));
}
template <int ACT>
__device__ __forceinline__ float act_apply(float v) {
    if (ACT == 1) return fmaxf(v, 0.f);
    if (ACT == 2) return expf(v);
    if (ACT == 3) return 1.f / (1.f + expf(-v));
    return v;
}

#define CP_ASYNC16(dst, src, sz) \
    asm volatile("cp.async.cg.shared.global [%0], [%1], 16, %2;" \
                 :: "r"(dst), "l"(src), "r"(sz) : "memory")
#define CP_COMMIT() asm volatile("cp.async.commit_group;" ::: "memory")
template <int NW>
__device__ __forceinline__ void cp_wait() {
    asm volatile("cp.async.wait_group %0;" :: "n"(NW) : "memory");
}

__device__ __forceinline__ void ldsm4(uint32_t* r, uint32_t addr) {
    asm volatile("ldmatrix.sync.aligned.m8n8.x4.shared.b16 {%0,%1,%2,%3}, [%4];"
                 : "=r"(r[0]), "=r"(r[1]), "=r"(r[2]), "=r"(r[3]) : "r"(addr));
}
__device__ __forceinline__ void mma16816(float* d, const uint32_t* a, const uint32_t* b) {
    asm volatile(
        "mma.sync.aligned.m16n8k16.row.col.f32.bf16.bf16.f32 "
        "{%0,%1,%2,%3}, {%4,%5,%6,%7}, {%8,%9}, {%0,%1,%2,%3};"
        : "+f"(d[0]), "+f"(d[1]), "+f"(d[2]), "+f"(d[3])
        : "r"(a[0]), "r"(a[1]), "r"(a[2]), "r"(a[3]), "r"(b[0]), "r"(b[1]));
}

// Row stride 64B (32 bf16); XOR-swizzle 16B chunks: chunkpos = chunk ^ ((row>>1)&3)
__device__ __forceinline__ uint32_t swoff(int row, int chunk) {
    return ((uint32_t)row << 6) + ((uint32_t)((chunk ^ ((row >> 1) & 3))) << 4);
}

// ---------------- split kernels -------------------------------------------
__global__ void split_a4(const float* __restrict__ A, __nv_bfloat16* __restrict__ hi,
                         __nv_bfloat16* __restrict__ lo) {
    const int per_row = KP_X / 4;  // 208
    long i = (long)blockIdx.x * blockDim.x + threadIdx.x;
    if (i >= (long)BATCH * per_row) return;
    int k4 = (int)(i % per_row);
    long r = i / per_row;
    int k = k4 * 4;
    float4 v = make_float4(0.f, 0.f, 0.f, 0.f);
    if (k < 784) v = *(const float4*)(A + r * 784 + k);
    __nv_bfloat16 h[4], l[4];
    split2(v.x, h[0], l[0]);
    split2(v.y, h[1], l[1]);
    split2(v.z, h[2], l[2]);
    split2(v.w, h[3], l[3]);
    *(uint2*)(hi + r * KP_X + k) = *(uint2*)h;
    *(uint2*)(lo + r * KP_X + k) = *(uint2*)l;
}

// W [K,N] fp32 -> out [Np,Kp] bf16 (transposed, padded), smem-tiled transpose
__global__ void __launch_bounds__(256)
split_wt(const float* __restrict__ W, __nv_bfloat16* __restrict__ hi,
         __nv_bfloat16* __restrict__ lo, int K, int N, int Kp, int Np) {
    __shared__ float s[32][33];
    const int tx = threadIdx.x & 31, ty = threadIdx.x >> 5;  // 32x8
    const int tileN = blockIdx.x * 32, tileK = blockIdx.y * 32;
#pragma unroll
    for (int r = 0; r < 4; r++) {
        int kk = tileK + ty + r * 8, nn = tileN + tx;
        s[ty + r * 8][tx] = (kk < K && nn < N) ? W[(size_t)kk * N + nn] : 0.f;
    }
    __syncthreads();
#pragma unroll
    for (int r = 0; r < 4; r++) {
        int nn = tileN + ty + r * 8, kk = tileK + tx;
        if (nn < Np && kk < Kp) {
            __nv_bfloat16 h, l;
            split2(s[tx][ty + r * 8], h, l);
            hi[(size_t)nn * Kp + kk] = h;
            lo[(size_t)nn * Kp + kk] = l;
        }
    }
}

// Build fused mu|eigen weight buffer [256,KP_H] + combined bias [256]
__global__ void prep_me(const float* __restrict__ Wmu, const float* __restrict__ bmu,
                        const float* __restrict__ We, const float* __restrict__ be,
                        __nv_bfloat16* __restrict__ hi, __nv_bfloat16* __restrict__ lo,
                        float* __restrict__ bias) {
    int i = blockIdx.x * blockDim.x + threadIdx.x;
    if (i < 256) {
        bias[i] = (i < 100) ? bmu[i] : ((i >= 128 && i < 228) ? be[i - 128] : 0.f);
    }
    if (i >= 256 * KP_H) return;
    int n = i / KP_H, k = i % KP_H;
    float v = 0.f;
    if (k < 400) {
        if (n < 100) v = Wmu[(size_t)k * 100 + n];
        else if (n >= 128 && n < 228) v = We[(size_t)k * 100 + (n - 128)];
    }
    __nv_bfloat16 h, l;
    split2(v, h, l);
    hi[i] = h;
    lo[i] = l;
}

// ---------------- 3-term bf16 split GEMM on mma.sync -----------------------
// C[M,N] = act((Ahi+Alo)[M,Kp] @ ((Bhi+Blo)[N,Kp])^T + bias)
// 128x128x32 CTA tile, 8 warps (4x2), warp tile 32x64, 3-stage cp.async,
// 2 CTAs/SM. Per-bi inner loop ordered by term (hi*hi, lo*hi, hi*lo) so each
// accumulator's reuse distance is 4 independent MMAs.
#define STAGES 3
#define STAGE_BYTES 32768
#define GEMM_SMEM (STAGES * STAGE_BYTES)

template <int ACT, bool SPLIT_OUT>
__global__ void __launch_bounds__(256, 2)
mma_gemm(const __nv_bfloat16* __restrict__ Ahi, const __nv_bfloat16* __restrict__ Alo,
         const __nv_bfloat16* __restrict__ Bhi, const __nv_bfloat16* __restrict__ Blo,
         const float* __restrict__ bias, float* __restrict__ C, float* __restrict__ C2,
         __nv_bfloat16* __restrict__ outHi, __nv_bfloat16* __restrict__ outLo,
         int N, int Kp, int ldOut) {
    extern __shared__ char smem[];
    const uint32_t sbase = smem_u32(smem);
    const int tid = threadIdx.x, wid = tid >> 5, lane = tid & 31;
    const int wm = wid >> 1, wn = wid & 1;
    const int rowBase = blockIdx.y * 128, colBase = blockIdx.x * 128;
    const int NC = Kp >> 5;

    float acc[2][8][4];
#pragma unroll
    for (int i = 0; i < 2; i++)
#pragma unroll
        for (int j = 0; j < 8; j++)
#pragma unroll
            for (int q = 0; q < 4; q++) acc[i][j][q] = 0.f;

    auto load_stage = [&](int c, int stg) {
        const int kBase = c << 5;
        const uint32_t sb = sbase + stg * STAGE_BYTES;
#pragma unroll
        for (int t = 0; t < 4; t++) {
            const __nv_bfloat16* P = (t == 0) ? Ahi : (t == 1) ? Alo
                                   : (t == 2) ? Bhi : Blo;
            const bool isB = (t >= 2);
#pragma unroll
            for (int i = 0; i < 2; i++) {
                int cid = tid + i * 256;          // 0..511
                int row = cid >> 2, ch = cid & 3;
                uint32_t dst = sb + t * 8192 + swoff(row, ch);
                int gr, sz = 16;
                if (isB) {
                    gr = colBase + row;
                    if (gr >= N) { gr = 0; sz = 0; }
                } else {
                    gr = rowBase + row;
                }
                const void* src = P + (size_t)gr * Kp + kBase + ch * 8;
                CP_ASYNC16(dst, src, sz);
            }
        }
    };

    load_stage(0, 0);
    CP_COMMIT();
    load_stage(1, 1);
    CP_COMMIT();

    for (int c = 0; c < NC; c++) {
        cp_wait<STAGES - 2>();
        __syncthreads();
        if (c + STAGES - 1 < NC) {
            load_stage(c + STAGES - 1, (c + STAGES - 1) % STAGES);
            CP_COMMIT();
        }
        const uint32_t sb = sbase + (c % STAGES) * STAGE_BYTES;
#pragma unroll
        for (int kk = 0; kk < 2; kk++) {
            uint32_t ahi[2][4], alo[2][4];
#pragma unroll
            for (int mi = 0; mi < 2; mi++) {
                int row = wm * 32 + mi * 16 + (lane & 15);
                int ch = kk * 2 + (lane >> 4);
                uint32_t o = swoff(row, ch);
                ldsm4(ahi[mi], sb + o);
                ldsm4(alo[mi], sb + 8192 + o);
            }
#pragma unroll
            for (int bi = 0; bi < 4; bi++) {
                int row = wn * 64 + bi * 16 + (lane & 7) + ((lane >> 4) << 3);
                int ch = kk * 2 + ((lane >> 3) & 1);
                uint32_t o = swoff(row, ch);
                uint32_t bhi[4], blo[4];
                ldsm4(bhi, sb + 16384 + o);
                ldsm4(blo, sb + 24576 + o);
                // term-major: 4 distinct accumulators between dependent issues
                // hi * hi
                mma16816(acc[0][2 * bi],     ahi[0], bhi);
                mma16816(acc[0][2 * bi + 1], ahi[0], bhi + 2);
                mma16816(acc[1][2 * bi],     ahi[1], bhi);
                mma16816(acc[1][2 * bi + 1], ahi[1], bhi + 2);
                // lo * hi
                mma16816(acc[0][2 * bi],     alo[0], bhi);
                mma16816(acc[0][2 * bi + 1], alo[0], bhi + 2);
                mma16816(acc[1][2 * bi],     alo[1], bhi);
                mma16816(acc[1][2 * bi + 1], alo[1], bhi + 2);
                // hi * lo
                mma16816(acc[0][2 * bi],     ahi[0], blo);
                mma16816(acc[0][2 * bi + 1], ahi[0], blo + 2);
                mma16816(acc[1][2 * bi],     ahi[1], blo);
                mma16816(acc[1][2 * bi + 1], ahi[1], blo + 2);
            }
        }
    }

    // ---------------- epilogue ----------------
#pragma unroll
    for (int mi = 0; mi < 2; mi++) {
#pragma unroll
        for (int ni = 0; ni < 8; ni++) {
            const float* a4 = acc[mi][ni];
            const int r0 = rowBase + wm * 32 + mi * 16 + (lane >> 2);
            const int col = colBase + wn * 64 + ni * 8 + ((lane & 3) << 1);
            float b0 = (col < N) ? bias[col] : 0.f;
            float b1 = (col + 1 < N) ? bias[col + 1] : 0.f;
#pragma unroll
            for (int h = 0; h < 2; h++) {
                const size_t row = (size_t)(r0 + h * 8);
                if (ACT == 4) {
                    float v0 = a4[2 * h + 0] + b0;
                    float v1 = a4[2 * h + 1] + b1;
                    if (col < 100) C[row * 100 + col] = v0;
                    else if (col >= 128 && col < 228) C2[row * 100 + col - 128] = expf(v0);
                    if (col + 1 < 100) C[row * 100 + col + 1] = v1;
                    else if (col + 1 >= 128 && col + 1 < 228) C2[row * 100 + col + 1 - 128] = expf(v1);
                    continue;
                }
                const float v0 = act_apply<ACT>(a4[2 * h + 0] + b0);
                const float v1 = act_apply<ACT>(a4[2 * h + 1] + b1);
                if (SPLIT_OUT) {
                    if (col < N) {
                        __nv_bfloat16 hh, ll;
                        split2(v0, hh, ll);
                        outHi[row * ldOut + col] = hh;
                        outLo[row * ldOut + col] = ll;
                        if (col + 1 < N) {
                            split2(v1, hh, ll);
                            outHi[row * ldOut + col + 1] = hh;
                            outLo[row * ldOut + col + 1] = ll;
                        } else if (col + 1 < ldOut) {
                            outHi[row * ldOut + col + 1] = __float2bfloat16(0.f);
                            outLo[row * ldOut + col + 1] = __float2bfloat16(0.f);
                        }
                    } else if (col < ldOut) {
                        outHi[row * ldOut + col] = __float2bfloat16(0.f);
                        outLo[row * ldOut + col] = __float2bfloat16(0.f);
                        if (col + 1 < ldOut) {
                            outHi[row * ldOut + col + 1] = __float2bfloat16(0.f);
                            outLo[row * ldOut + col + 1] = __float2bfloat16(0.f);
                        }
                    }
                } else {
                    if (col < N) C[row * ldOut + col] = v0;
                    if (col + 1 < N) C[row * ldOut + col + 1] = v1;
                }
            }
        }
    }
}

// ---------------- per-row solve kernel ------------------------------------
__global__ void __launch_bounds__(256)
solve_kernel(const float* __restrict__ Wa, const float* __restrict__ ba,
             const float* __restrict__ u, const float* __restrict__ eps,
             const __nv_bfloat16* __restrict__ h1hi, const __nv_bfloat16* __restrict__ h1lo,
             const float* __restrict__ outQ, const float* __restrict__ outMu,
             const float* __restrict__ outEig, float* __restrict__ outA,
             float* __restrict__ z) {
    __shared__ float Qs[8][400];
    const unsigned FULL = 0xffffffffu;
    const int w = threadIdx.x >> 5, lane = threadIdx.x & 31;
    const int row = blockIdx.x * 8 + w;

    float s0 = 0, s1 = 0, s2 = 0, s3 = 0, s4 = 0;
    const __nv_bfloat16* hh = h1hi + (size_t)row * KP_H;
    const __nv_bfloat16* hl = h1lo + (size_t)row * KP_H;
    for (int k = lane; k < 400; k += 32) {
        float h = __bfloat162float(hh[k]) + __bfloat162float(hl[k]);
        const float* wk = Wa + k * 5;
        s0 = fmaf(h, wk[0], s0);
        s1 = fmaf(h, wk[1], s1);
        s2 = fmaf(h, wk[2], s2);
        s3 = fmaf(h, wk[3], s3);
        s4 = fmaf(h, wk[4], s4);
    }
#pragma unroll
    for (int off = 16; off; off >>= 1) {
        s0 += __shfl_xor_sync(FULL, s0, off);
        s1 += __shfl_xor_sync(FULL, s1, off);
        s2 += __shfl_xor_sync(FULL, s2, off);
        s3 += __shfl_xor_sync(FULL, s3, off);
        s4 += __shfl_xor_sync(FULL, s4, off);
    }
    s0 += ba[0]; s1 += ba[1]; s2 += ba[2]; s3 += ba[3]; s4 += ba[4];
    float mx = fmaxf(fmaxf(fmaxf(s0, s1), fmaxf(s2, s3)), s4);
    float e0 = expf(s0 - mx), e1 = expf(s1 - mx), e2 = expf(s2 - mx),
          e3 = expf(s3 - mx), e4 = expf(s4 - mx);
    float inv = 1.f / (e0 + e1 + e2 + e3 + e4);
    float av[5] = {e0 * inv, e1 * inv, e2 * inv, e3 * inv, e4 * inv};
    if (lane == 0) {
        float* ar = outA + (size_t)row * 5;
        ar[0] = av[0]; ar[1] = av[1]; ar[2] = av[2]; ar[3] = av[3]; ar[4] = av[4];
    }

    float uu = u[row];
    int idx = 0;
    bool found = false;
    float c = 0.f;
#pragma unroll
    for (int j = 0; j < 5; j++) {
        c += av[j];
        if (!found && uu < c) { idx = j; found = true; }
    }

    const float* Qr = outQ + (size_t)row * 2000 + idx * 400;
    for (int k = lane; k < 400; k += 32) Qs[w][k] = Qr[k];
    __syncwarp();

    float o[20], r[20];
    float rhs = 0.f, eig = 0.f, mui = 0.f;
    if (lane < 20) {
#pragma unroll
        for (int j = 0; j < 20; j++) o[j] = Qs[w][lane * 20 + j];
        rhs = eps[(size_t)row * 20 + lane];
        eig = outEig[(size_t)row * 100 + idx * 20 + lane];
        mui = outMu[(size_t)row * 100 + idx * 20 + lane];
    } else {
#pragma unroll
        for (int j = 0; j < 20; j++) o[j] = 0.f;
    }
#pragma unroll
    for (int j = 0; j < 20; j++) r[j] = o[j];

#pragma unroll
    for (int k = 0; k < 20; k++) {
        float key = (lane >= k && lane < 20) ? fabsf(r[k]) : -1.0f;
        int pi = lane;
#pragma unroll
        for (int off = 16; off; off >>= 1) {
            float ok = __shfl_xor_sync(FULL, key, off);
            int oi = __shfl_xor_sync(FULL, pi, off);
            if (ok > key || (ok == key && oi < pi)) { key = ok; pi = oi; }
        }
        if (pi != k) {
            int partner = (lane == k) ? pi : ((lane == pi) ? k : lane);
#pragma unroll
            for (int j = 0; j < 20; j++) r[j] = __shfl_sync(FULL, r[j], partner);
            rhs = __shfl_sync(FULL, rhs, partner);
        }
        float akk = __shfl_sync(FULL, r[k], k);
        float m = (lane > k && lane < 20) ? r[k] / akk : 0.0f;
        float rk = __shfl_sync(FULL, rhs, k);
        rhs = fmaf(-m, rk, rhs);
#pragma unroll
        for (int j = k + 1; j < 20; j++) {
            float akj = __shfl_sync(FULL, r[j], k);
            r[j] = fmaf(-m, akj, r[j]);
        }
    }

    float y = 0.f;
#pragma unroll
    for (int k = 19; k >= 0; k--) {
        float num = __shfl_sync(FULL, rhs, k);
        float akk = __shfl_sync(FULL, r[k], k);
        float yk = num / akk;
        if (lane == k) y = yk;
        if (lane < k) rhs = fmaf(-r[k], yk, rhs);
    }

    float wv = eig * y;
    float zv = mui;
#pragma unroll
    for (int j = 0; j < 20; j++) {
        float wj = __shfl_sync(FULL, wv, j);
        zv = fmaf(o[j], wj, zv);
    }
    if (lane < 20) z[(size_t)row * 20 + lane] = zv;
}

// ---------------- h3 = relu(z@W3+b3) -> bf16 hi/lo (pads cols 400..447) ---
__global__ void __launch_bounds__(128)
h3_kernel(const float* __restrict__ z, const float* __restrict__ W3,
          const float* __restrict__ b3, __nv_bfloat16* __restrict__ h3hi,
          __nv_bfloat16* __restrict__ h3lo) {
    __shared__ float zs[32 * 20];
    const int col = blockIdx.x * 128 + threadIdx.x;
    const int row0 = blockIdx.y * 32;
    for (int i = threadIdx.x; i < 32 * 20; i += 128)
        zs[i] = z[(size_t)row0 * 20 + i];
    __syncthreads();

    if (col < KP_H) {
        if (col < 400) {
            float wcol[20];
#pragma unroll
            for (int k = 0; k < 20; k++) wcol[k] = W3[k * 400 + col];
            float bias = b3[col];
            for (int rr = 0; rr < 32; rr++) {
                float acc = bias;
#pragma unroll
                for (int k = 0; k < 20; k++)
                    acc = fmaf(zs[rr * 20 + k], wcol[k], acc);
                float v = fmaxf(acc, 0.f);
                __nv_bfloat16 h, l;
                split2(v, h, l);
                h3hi[(size_t)(row0 + rr) * KP_H + col] = h;
                h3lo[(size_t)(row0 + rr) * KP_H + col] = l;
            }
        } else {
            for (int rr = 0; rr < 32; rr++) {
                h3hi[(size_t)(row0 + rr) * KP_H + col] = __float2bfloat16(0.f);
                h3lo[(size_t)(row0 + rr) * KP_H + col] = __float2bfloat16(0.f);
            }
        }
    }
}

// ---------------- launch ---------------------------------------------------
extern "C" void kernel_launch(void* const* d_in, const int* in_sizes, int n_in,
                              void* d_out, int out_size) {
    const float* x   = (const float*)d_in[0];
    const float* u   = (const float*)d_in[1];
    const float* eps = (const float*)d_in[2];
    const float* W1  = (const float*)d_in[3];
    const float* b1  = (const float*)d_in[4];
    const float* Wmu = (const float*)d_in[5];
    const float* bmu = (const float*)d_in[6];
    const float* WQ  = (const float*)d_in[7];
    const float* bQ  = (const float*)d_in[8];
    const float* Wa  = (const float*)d_in[9];
    const float* ba  = (const float*)d_in[10];
    const float* We  = (const float*)d_in[11];
    const float* be  = (const float*)d_in[12];
    const float* W3  = (const float*)d_in[13];
    const float* b3  = (const float*)d_in[14];
    const float* W4  = (const float*)d_in[15];
    const float* b4  = (const float*)d_in[16];

    float* out = (float*)d_out;
    float* out_recon = out;
    float* out_mu    = out_recon + (size_t)BATCH * 784;
    float* out_Q     = out_mu    + (size_t)BATCH * 100;
    float* out_a     = out_Q     + (size_t)BATCH * 2000;
    float* out_eig   = out_a     + (size_t)BATCH * 5;

    __nv_bfloat16 *xhi, *xlo, *h1hi, *h1lo, *h3hi, *h3lo;
    __nv_bfloat16 *B1hi, *B1lo, *BQhi, *BQlo, *Bmehi, *Bmelo, *B4hi, *B4lo;
    float *zp, *bme;
    cudaGetSymbolAddress((void**)&xhi, g_xhi);
    cudaGetSymbolAddress((void**)&xlo, g_xlo);
    cudaGetSymbolAddress((void**)&h1hi, g_h1hi);
    cudaGetSymbolAddress((void**)&h1lo, g_h1lo);
    cudaGetSymbolAddress((void**)&h3hi, g_h3hi);
    cudaGetSymbolAddress((void**)&h3lo, g_h3lo);
    cudaGetSymbolAddress((void**)&B1hi, g_B1hi);
    cudaGetSymbolAddress((void**)&B1lo, g_B1lo);
    cudaGetSymbolAddress((void**)&BQhi, g_BQhi);
    cudaGetSymbolAddress((void**)&BQlo, g_BQlo);
    cudaGetSymbolAddress((void**)&Bmehi, g_Bmehi);
    cudaGetSymbolAddress((void**)&Bmelo, g_Bmelo);
    cudaGetSymbolAddress((void**)&bme, g_bme);
    cudaGetSymbolAddress((void**)&B4hi, g_B4hi);
    cudaGetSymbolAddress((void**)&B4lo, g_B4lo);
    cudaGetSymbolAddress((void**)&zp, g_z);

    cudaFuncSetAttribute(mma_gemm<1, true>,  cudaFuncAttributeMaxDynamicSharedMemorySize, GEMM_SMEM);
    cudaFuncSetAttribute(mma_gemm<2, false>, cudaFuncAttributeMaxDynamicSharedMemorySize, GEMM_SMEM);
    cudaFuncSetAttribute(mma_gemm<4, false>, cudaFuncAttributeMaxDynamicSharedMemorySize, GEMM_SMEM);
    cudaFuncSetAttribute(mma_gemm<3, false>, cudaFuncAttributeMaxDynamicSharedMemorySize, GEMM_SMEM);

    // #1 x split (vectorized)
    {
        long tot = (long)BATCH * (KP_X / 4);
        split_a4<<<(unsigned)((tot + 255) / 256), 256>>>(x, xhi, xlo);
    }
    // #2 W1 split (tiled transpose)
    split_wt<<<dim3((400 + 31) / 32, (KP_X + 31) / 32), 256>>>(W1, B1hi, B1lo, 784, 400, KP_X, 400);
    // #3 WQ split
    split_wt<<<dim3((2000 + 31) / 32, (KP_H + 31) / 32), 256>>>(WQ, BQhi, BQlo, 400, 2000, KP_H, 2000);
    // #4 fused mu|eigen weight + bias prep
    prep_me<<<(256 * KP_H + 255) / 256, 256>>>(Wmu, bmu, We, be, Bmehi, Bmelo, bme);
    // #5 h1 = relu(x@W1+b1) -> bf16 hi/lo
    mma_gemm<1, true><<<dim3(4, 256), 256, GEMM_SMEM>>>(
        xhi, xlo, B1hi, B1lo, b1, nullptr, nullptr, h1hi, h1lo, 400, KP_X, KP_H);
    // #6 Q = exp(h1@WQ+bQ)
    mma_gemm<2, false><<<dim3(16, 256), 256, GEMM_SMEM>>>(
        h1hi, h1lo, BQhi, BQlo, bQ, out_Q, nullptr, nullptr, nullptr, 2000, KP_H, 2000);
    // #7 W4 split
    split_wt<<<dim3((784 + 31) / 32, (KP_H + 31) / 32), 256>>>(W4, B4hi, B4lo, 400, 784, KP_H, 784);
    // #8 fused mu + eigen GEMM (N=256)
    mma_gemm<4, false><<<dim3(2, 256), 256, GEMM_SMEM>>>(
        h1hi, h1lo, Bmehi, Bmelo, bme, out_mu, out_eig, nullptr, nullptr, 256, KP_H, 100);
    // #9 softmax / idx / LU solve / z
    solve_kernel<<<BATCH / 8, 256>>>(Wa, ba, u, eps, h1hi, h1lo, out_Q, out_mu,
                                     out_eig, out_a, zp);
    // #10 h3 = relu(z@W3+b3) -> bf16 hi/lo
    h3_kernel<<<dim3(4, BATCH / 32), 128>>>(zp, W3, b3, h3hi, h3lo);
    // #11 recon = sigmoid(h3@W4+b4)
    mma_gemm<3, false><<<dim3(7, 256), 256, GEMM_SMEM>>>(
        h3hi, h3lo, B4hi, B4lo, b4, out_recon, nullptr, nullptr, nullptr, 784, KP_H, 784);
}

// round 7
// speedup vs baseline: 1.2169x; 1.0027x over previous
#include <cuda_runtime.h>
#include <cuda_bf16.h>
#include <math.h>
#include <stdint.h>

#define BATCH 32768
#define KP_X 784   // exact: 49 chunks of 16
#define KP_H 400   // exact: 25 chunks of 16

// ---------------- scratch (__device__ globals; no cudaMalloc allowed) ------
__device__ __align__(256) __nv_bfloat16 g_xhi[BATCH * KP_X];
__device__ __align__(256) __nv_bfloat16 g_xlo[BATCH * KP_X];
__device__ __align__(256) __nv_bfloat16 g_h1hi[BATCH * KP_H];
__device__ __align__(256) __nv_bfloat16 g_h1lo[BATCH * KP_H];
__device__ __align__(256) __nv_bfloat16 g_h3hi[BATCH * KP_H];
__device__ __align__(256) __nv_bfloat16 g_h3lo[BATCH * KP_H];
__device__ __align__(256) __nv_bfloat16 g_B1hi[400 * KP_X];
__device__ __align__(256) __nv_bfloat16 g_B1lo[400 * KP_X];
__device__ __align__(256) __nv_bfloat16 g_BQhi[2000 * KP_H];
__device__ __align__(256) __nv_bfloat16 g_BQlo[2000 * KP_H];
__device__ __align__(256) __nv_bfloat16 g_Bmehi[256 * KP_H];
__device__ __align__(256) __nv_bfloat16 g_Bmelo[256 * KP_H];
__device__ __align__(256) float g_bme[256];
__device__ __align__(256) __nv_bfloat16 g_B4hi[784 * KP_H];
__device__ __align__(256) __nv_bfloat16 g_B4lo[784 * KP_H];
__device__ float g_z[BATCH * 20];

// ---------------- helpers --------------------------------------------------
__device__ __forceinline__ uint32_t smem_u32(const void* p) {
    uint32_t a;
    asm("{ .reg .u64 t; cvta.to.shared.u64 t, %1; cvt.u32.u64 %0, t; }"
        : "=r"(a) : "l"(p));
    return a;
}
__device__ __forceinline__ void split2(float v, __nv_bfloat16& hi, __nv_bfloat16& lo) {
    hi = __float2bfloat16(v);
    lo = __float2bfloat16(v - __bfloat162float(hi));
}
template <int ACT>
__device__ __forceinline__ float act_apply(float v) {
    if (ACT == 1) return fmaxf(v, 0.f);
    if (ACT == 2) return expf(v);
    if (ACT == 3) return 1.f / (1.f + expf(-v));
    return v;
}

#define CP_ASYNC16(dst, src, sz) \
    asm volatile("cp.async.cg.shared.global [%0], [%1], 16, %2;" \
                 :: "r"(dst), "l"(src), "r"(sz) : "memory")
#define CP_COMMIT() asm volatile("cp.async.commit_group;" ::: "memory")
template <int NW>
__device__ __forceinline__ void cp_wait() {
    asm volatile("cp.async.wait_group %0;" :: "n"(NW) : "memory");
}

__device__ __forceinline__ void ldsm4(uint32_t* r, uint32_t addr) {
    asm volatile("ldmatrix.sync.aligned.m8n8.x4.shared.b16 {%0,%1,%2,%3}, [%4];"
                 : "=r"(r[0]), "=r"(r[1]), "=r"(r[2]), "=r"(r[3]) : "r"(addr));
}
__device__ __forceinline__ void mma16816(float* d, const uint32_t* a, const uint32_t* b) {
    asm volatile(
        "mma.sync.aligned.m16n8k16.row.col.f32.bf16.bf16.f32 "
        "{%0,%1,%2,%3}, {%4,%5,%6,%7}, {%8,%9}, {%0,%1,%2,%3};"
        : "+f"(d[0]), "+f"(d[1]), "+f"(d[2]), "+f"(d[3])
        : "r"(a[0]), "r"(a[1]), "r"(a[2]), "r"(a[3]), "r"(b[0]), "r"(b[1]));
}

// BK=16: row stride 32B (2 x 16B chunks); conflict-free swizzle:
// pos = ch ^ ((row>>2)&1)  -> distinct 16B banks mod 8 per 8-lane phase
__device__ __forceinline__ uint32_t swoff16(int row, int ch) {
    return ((uint32_t)row << 5) + ((uint32_t)(ch ^ ((row >> 2) & 1)) << 4);
}

// ---------------- split kernels -------------------------------------------
__global__ void split_a4(const float* __restrict__ A, __nv_bfloat16* __restrict__ hi,
                         __nv_bfloat16* __restrict__ lo) {
    const int per_row = KP_X / 4;  // 196, exact
    long i = (long)blockIdx.x * blockDim.x + threadIdx.x;
    if (i >= (long)BATCH * per_row) return;
    int k = (int)(i % per_row) * 4;
    long r = i / per_row;
    float4 v = *(const float4*)(A + r * KP_X + k);
    __nv_bfloat16 h[4], l[4];
    split2(v.x, h[0], l[0]);
    split2(v.y, h[1], l[1]);
    split2(v.z, h[2], l[2]);
    split2(v.w, h[3], l[3]);
    *(uint2*)(hi + r * KP_X + k) = *(uint2*)h;
    *(uint2*)(lo + r * KP_X + k) = *(uint2*)l;
}

// W [K,N] fp32 -> out [Np,Kp] bf16 (transposed), smem-tiled transpose
__global__ void __launch_bounds__(256)
split_wt(const float* __restrict__ W, __nv_bfloat16* __restrict__ hi,
         __nv_bfloat16* __restrict__ lo, int K, int N, int Kp, int Np) {
    __shared__ float s[32][33];
    const int tx = threadIdx.x & 31, ty = threadIdx.x >> 5;  // 32x8
    const int tileN = blockIdx.x * 32, tileK = blockIdx.y * 32;
#pragma unroll
    for (int r = 0; r < 4; r++) {
        int kk = tileK + ty + r * 8, nn = tileN + tx;
        s[ty + r * 8][tx] = (kk < K && nn < N) ? W[(size_t)kk * N + nn] : 0.f;
    }
    __syncthreads();
#pragma unroll
    for (int r = 0; r < 4; r++) {
        int nn = tileN + ty + r * 8, kk = tileK + tx;
        if (nn < Np && kk < Kp) {
            __nv_bfloat16 h, l;
            split2(s[tx][ty + r * 8], h, l);
            hi[(size_t)nn * Kp + kk] = h;
            lo[(size_t)nn * Kp + kk] = l;
        }
    }
}

// Build fused mu|eigen weight buffer [256,KP_H] + combined bias [256]
__global__ void prep_me(const float* __restrict__ Wmu, const float* __restrict__ bmu,
                        const float* __restrict__ We, const float* __restrict__ be,
                        __nv_bfloat16* __restrict__ hi, __nv_bfloat16* __restrict__ lo,
                        float* __restrict__ bias) {
    int i = blockIdx.x * blockDim.x + threadIdx.x;
    if (i < 256) {
        bias[i] = (i < 100) ? bmu[i] : ((i >= 128 && i < 228) ? be[i - 128] : 0.f);
    }
    if (i >= 256 * KP_H) return;
    int n = i / KP_H, k = i % KP_H;
    float v = 0.f;
    if (n < 100) v = Wmu[(size_t)k * 100 + n];
    else if (n >= 128 && n < 228) v = We[(size_t)k * 100 + (n - 128)];
    __nv_bfloat16 h, l;
    split2(v, h, l);
    hi[i] = h;
    lo[i] = l;
}

// ---------------- 3-term bf16 split GEMM on mma.sync -----------------------
// C[M,N] = act((Ahi+Alo)[M,Kp] @ ((Bhi+Blo)[N,Kp])^T + bias)
// 128x128x16 CTA tile, 8 warps (4x2), warp tile 32x64, 4-stage cp.async,
// 2 CTAs/SM. K exact (no padding waste).
#define STAGES 4
#define STAGE_BYTES 16384
#define GEMM_SMEM (STAGES * STAGE_BYTES)

template <int ACT, bool SPLIT_OUT>
__global__ void __launch_bounds__(256, 2)
mma_gemm(const __nv_bfloat16* __restrict__ Ahi, const __nv_bfloat16* __restrict__ Alo,
         const __nv_bfloat16* __restrict__ Bhi, const __nv_bfloat16* __restrict__ Blo,
         const float* __restrict__ bias, float* __restrict__ C, float* __restrict__ C2,
         __nv_bfloat16* __restrict__ outHi, __nv_bfloat16* __restrict__ outLo,
         int N, int Kp, int ldOut) {
    extern __shared__ char smem[];
    const uint32_t sbase = smem_u32(smem);
    const int tid = threadIdx.x, wid = tid >> 5, lane = tid & 31;
    const int wm = wid >> 1, wn = wid & 1;
    const int rowBase = blockIdx.y * 128, colBase = blockIdx.x * 128;
    const int NC = Kp >> 4;

    float acc[2][8][4];
#pragma unroll
    for (int i = 0; i < 2; i++)
#pragma unroll
        for (int j = 0; j < 8; j++)
#pragma unroll
            for (int q = 0; q < 4; q++) acc[i][j][q] = 0.f;

    // per-stage: 4 tensors x (128 rows x 16 bf16 = 32B) = 4KB each
    auto load_stage = [&](int c, int stg) {
        const int kBase = c << 4;
        const uint32_t sb = sbase + stg * STAGE_BYTES;
        const int row = tid >> 1, ch = tid & 1;
        const uint32_t o = swoff16(row, ch);
        const int arow = rowBase + row;
        int brow = colBase + row, bsz = 16;
        if (brow >= N) { brow = 0; bsz = 0; }
        const size_t aoff = (size_t)arow * Kp + kBase + ch * 8;
        const size_t boff = (size_t)brow * Kp + kBase + ch * 8;
        CP_ASYNC16(sb + o, Ahi + aoff, 16);
        CP_ASYNC16(sb + 4096 + o, Alo + aoff, 16);
        CP_ASYNC16(sb + 8192 + o, Bhi + boff, bsz);
        CP_ASYNC16(sb + 12288 + o, Blo + boff, bsz);
    };

    load_stage(0, 0);
    CP_COMMIT();
    load_stage(1, 1);
    CP_COMMIT();
    load_stage(2, 2);
    CP_COMMIT();

    for (int c = 0; c < NC; c++) {
        cp_wait<STAGES - 2>();
        __syncthreads();
        if (c + STAGES - 1 < NC) {
            load_stage(c + STAGES - 1, (c + STAGES - 1) % STAGES);
            CP_COMMIT();
        }
        const uint32_t sb = sbase + (c % STAGES) * STAGE_BYTES;

        uint32_t ahi[2][4], alo[2][4];
#pragma unroll
        for (int mi = 0; mi < 2; mi++) {
            int row = wm * 32 + mi * 16 + (lane & 15);
            int ch = lane >> 4;
            uint32_t o = swoff16(row, ch);
            ldsm4(ahi[mi], sb + o);
            ldsm4(alo[mi], sb + 4096 + o);
        }
#pragma unroll
        for (int bi = 0; bi < 4; bi++) {
            int row = wn * 64 + bi * 16 + (lane & 7) + ((lane >> 4) << 3);
            int ch = (lane >> 3) & 1;
            uint32_t o = swoff16(row, ch);
            uint32_t bhi[4], blo[4];
            ldsm4(bhi, sb + 8192 + o);
            ldsm4(blo, sb + 12288 + o);
            // term-major ordering: reuse distance 4 per accumulator
            mma16816(acc[0][2 * bi],     ahi[0], bhi);
            mma16816(acc[0][2 * bi + 1], ahi[0], bhi + 2);
            mma16816(acc[1][2 * bi],     ahi[1], bhi);
            mma16816(acc[1][2 * bi + 1], ahi[1], bhi + 2);
            mma16816(acc[0][2 * bi],     alo[0], bhi);
            mma16816(acc[0][2 * bi + 1], alo[0], bhi + 2);
            mma16816(acc[1][2 * bi],     alo[1], bhi);
            mma16816(acc[1][2 * bi + 1], alo[1], bhi + 2);
            mma16816(acc[0][2 * bi],     ahi[0], blo);
            mma16816(acc[0][2 * bi + 1], ahi[0], blo + 2);
            mma16816(acc[1][2 * bi],     ahi[1], blo);
            mma16816(acc[1][2 * bi + 1], ahi[1], blo + 2);
        }
    }

    // ---------------- epilogue ----------------
#pragma unroll
    for (int mi = 0; mi < 2; mi++) {
#pragma unroll
        for (int ni = 0; ni < 8; ni++) {
            const float* a4 = acc[mi][ni];
            const int r0 = rowBase + wm * 32 + mi * 16 + (lane >> 2);
            const int col = colBase + wn * 64 + ni * 8 + ((lane & 3) << 1);
            float b0 = (col < N) ? bias[col] : 0.f;
            float b1 = (col + 1 < N) ? bias[col + 1] : 0.f;
#pragma unroll
            for (int h = 0; h < 2; h++) {
                const size_t row = (size_t)(r0 + h * 8);
                if (ACT == 4) {
                    float v0 = a4[2 * h + 0] + b0;
                    float v1 = a4[2 * h + 1] + b1;
                    if (col < 100) C[row * 100 + col] = v0;
                    else if (col >= 128 && col < 228) C2[row * 100 + col - 128] = expf(v0);
                    if (col + 1 < 100) C[row * 100 + col + 1] = v1;
                    else if (col + 1 >= 128 && col + 1 < 228) C2[row * 100 + col + 1 - 128] = expf(v1);
                    continue;
                }
                const float v0 = act_apply<ACT>(a4[2 * h + 0] + b0);
                const float v1 = act_apply<ACT>(a4[2 * h + 1] + b1);
                if (SPLIT_OUT) {
                    if (col < N) {
                        __nv_bfloat16 hh, ll;
                        split2(v0, hh, ll);
                        outHi[row * ldOut + col] = hh;
                        outLo[row * ldOut + col] = ll;
                        if (col + 1 < N) {
                            split2(v1, hh, ll);
                            outHi[row * ldOut + col + 1] = hh;
                            outLo[row * ldOut + col + 1] = ll;
                        }
                    }
                } else {
                    if (col < N) C[row * ldOut + col] = v0;
                    if (col + 1 < N) C[row * ldOut + col + 1] = v1;
                }
            }
        }
    }
}

// ---------------- per-row solve kernel ------------------------------------
__global__ void __launch_bounds__(256)
solve_kernel(const float* __restrict__ Wa, const float* __restrict__ ba,
             const float* __restrict__ u, const float* __restrict__ eps,
             const __nv_bfloat16* __restrict__ h1hi, const __nv_bfloat16* __restrict__ h1lo,
             const float* __restrict__ outQ, const float* __restrict__ outMu,
             const float* __restrict__ outEig, float* __restrict__ outA,
             float* __restrict__ z) {
    __shared__ float Qs[8][400];
    const unsigned FULL = 0xffffffffu;
    const int w = threadIdx.x >> 5, lane = threadIdx.x & 31;
    const int row = blockIdx.x * 8 + w;

    float s0 = 0, s1 = 0, s2 = 0, s3 = 0, s4 = 0;
    const __nv_bfloat16* hh = h1hi + (size_t)row * KP_H;
    const __nv_bfloat16* hl = h1lo + (size_t)row * KP_H;
    for (int k = lane; k < 400; k += 32) {
        float h = __bfloat162float(hh[k]) + __bfloat162float(hl[k]);
        const float* wk = Wa + k * 5;
        s0 = fmaf(h, wk[0], s0);
        s1 = fmaf(h, wk[1], s1);
        s2 = fmaf(h, wk[2], s2);
        s3 = fmaf(h, wk[3], s3);
        s4 = fmaf(h, wk[4], s4);
    }
#pragma unroll
    for (int off = 16; off; off >>= 1) {
        s0 += __shfl_xor_sync(FULL, s0, off);
        s1 += __shfl_xor_sync(FULL, s1, off);
        s2 += __shfl_xor_sync(FULL, s2, off);
        s3 += __shfl_xor_sync(FULL, s3, off);
        s4 += __shfl_xor_sync(FULL, s4, off);
    }
    s0 += ba[0]; s1 += ba[1]; s2 += ba[2]; s3 += ba[3]; s4 += ba[4];
    float mx = fmaxf(fmaxf(fmaxf(s0, s1), fmaxf(s2, s3)), s4);
    float e0 = expf(s0 - mx), e1 = expf(s1 - mx), e2 = expf(s2 - mx),
          e3 = expf(s3 - mx), e4 = expf(s4 - mx);
    float inv = 1.f / (e0 + e1 + e2 + e3 + e4);
    float av[5] = {e0 * inv, e1 * inv, e2 * inv, e3 * inv, e4 * inv};
    if (lane == 0) {
        float* ar = outA + (size_t)row * 5;
        ar[0] = av[0]; ar[1] = av[1]; ar[2] = av[2]; ar[3] = av[3]; ar[4] = av[4];
    }

    float uu = u[row];
    int idx = 0;
    bool found = false;
    float c = 0.f;
#pragma unroll
    for (int j = 0; j < 5; j++) {
        c += av[j];
        if (!found && uu < c) { idx = j; found = true; }
    }

    const float* Qr = outQ + (size_t)row * 2000 + idx * 400;
    for (int k = lane; k < 400; k += 32) Qs[w][k] = Qr[k];
    __syncwarp();

    float o[20], r[20];
    float rhs = 0.f, eig = 0.f, mui = 0.f;
    if (lane < 20) {
#pragma unroll
        for (int j = 0; j < 20; j++) o[j] = Qs[w][lane * 20 + j];
        rhs = eps[(size_t)row * 20 + lane];
        eig = outEig[(size_t)row * 100 + idx * 20 + lane];
        mui = outMu[(size_t)row * 100 + idx * 20 + lane];
    } else {
#pragma unroll
        for (int j = 0; j < 20; j++) o[j] = 0.f;
    }
#pragma unroll
    for (int j = 0; j < 20; j++) r[j] = o[j];

#pragma unroll
    for (int k = 0; k < 20; k++) {
        float key = (lane >= k && lane < 20) ? fabsf(r[k]) : -1.0f;
        int pi = lane;
#pragma unroll
        for (int off = 16; off; off >>= 1) {
            float ok = __shfl_xor_sync(FULL, key, off);
            int oi = __shfl_xor_sync(FULL, pi, off);
            if (ok > key || (ok == key && oi < pi)) { key = ok; pi = oi; }
        }
        if (pi != k) {
            int partner = (lane == k) ? pi : ((lane == pi) ? k : lane);
#pragma unroll
            for (int j = 0; j < 20; j++) r[j] = __shfl_sync(FULL, r[j], partner);
            rhs = __shfl_sync(FULL, rhs, partner);
        }
        float akk = __shfl_sync(FULL, r[k], k);
        float m = (lane > k && lane < 20) ? r[k] / akk : 0.0f;
        float rk = __shfl_sync(FULL, rhs, k);
        rhs = fmaf(-m, rk, rhs);
#pragma unroll
        for (int j = k + 1; j < 20; j++) {
            float akj = __shfl_sync(FULL, r[j], k);
            r[j] = fmaf(-m, akj, r[j]);
        }
    }

    float y = 0.f;
#pragma unroll
    for (int k = 19; k >= 0; k--) {
        float num = __shfl_sync(FULL, rhs, k);
        float akk = __shfl_sync(FULL, r[k], k);
        float yk = num / akk;
        if (lane == k) y = yk;
        if (lane < k) rhs = fmaf(-r[k], yk, rhs);
    }

    float wv = eig * y;
    float zv = mui;
#pragma unroll
    for (int j = 0; j < 20; j++) {
        float wj = __shfl_sync(FULL, wv, j);
        zv = fmaf(o[j], wj, zv);
    }
    if (lane < 20) z[(size_t)row * 20 + lane] = zv;
}

// ---------------- h3 = relu(z@W3+b3) -> bf16 hi/lo -------------------------
__global__ void __launch_bounds__(128)
h3_kernel(const float* __restrict__ z, const float* __restrict__ W3,
          const float* __restrict__ b3, __nv_bfloat16* __restrict__ h3hi,
          __nv_bfloat16* __restrict__ h3lo) {
    __shared__ float zs[32 * 20];
    const int col = blockIdx.x * 128 + threadIdx.x;
    const int row0 = blockIdx.y * 32;
    for (int i = threadIdx.x; i < 32 * 20; i += 128)
        zs[i] = z[(size_t)row0 * 20 + i];
    __syncthreads();

    if (col < 400) {
        float wcol[20];
#pragma unroll
        for (int k = 0; k < 20; k++) wcol[k] = W3[k * 400 + col];
        float bias = b3[col];
        for (int rr = 0; rr < 32; rr++) {
            float acc = bias;
#pragma unroll
            for (int k = 0; k < 20; k++)
                acc = fmaf(zs[rr * 20 + k], wcol[k], acc);
            float v = fmaxf(acc, 0.f);
            __nv_bfloat16 h, l;
            split2(v, h, l);
            h3hi[(size_t)(row0 + rr) * KP_H + col] = h;
            h3lo[(size_t)(row0 + rr) * KP_H + col] = l;
        }
    }
}

// ---------------- launch ---------------------------------------------------
extern "C" void kernel_launch(void* const* d_in, const int* in_sizes, int n_in,
                              void* d_out, int out_size) {
    const float* x   = (const float*)d_in[0];
    const float* u   = (const float*)d_in[1];
    const float* eps = (const float*)d_in[2];
    const float* W1  = (const float*)d_in[3];
    const float* b1  = (const float*)d_in[4];
    const float* Wmu = (const float*)d_in[5];
    const float* bmu = (const float*)d_in[6];
    const float* WQ  = (const float*)d_in[7];
    const float* bQ  = (const float*)d_in[8];
    const float* Wa  = (const float*)d_in[9];
    const float* ba  = (const float*)d_in[10];
    const float* We  = (const float*)d_in[11];
    const float* be  = (const float*)d_in[12];
    const float* W3  = (const float*)d_in[13];
    const float* b3  = (const float*)d_in[14];
    const float* W4  = (const float*)d_in[15];
    const float* b4  = (const float*)d_in[16];

    float* out = (float*)d_out;
    float* out_recon = out;
    float* out_mu    = out_recon + (size_t)BATCH * 784;
    float* out_Q     = out_mu    + (size_t)BATCH * 100;
    float* out_a     = out_Q     + (size_t)BATCH * 2000;
    float* out_eig   = out_a     + (size_t)BATCH * 5;

    __nv_bfloat16 *xhi, *xlo, *h1hi, *h1lo, *h3hi, *h3lo;
    __nv_bfloat16 *B1hi, *B1lo, *BQhi, *BQlo, *Bmehi, *Bmelo, *B4hi, *B4lo;
    float *zp, *bme;
    cudaGetSymbolAddress((void**)&xhi, g_xhi);
    cudaGetSymbolAddress((void**)&xlo, g_xlo);
    cudaGetSymbolAddress((void**)&h1hi, g_h1hi);
    cudaGetSymbolAddress((void**)&h1lo, g_h1lo);
    cudaGetSymbolAddress((void**)&h3hi, g_h3hi);
    cudaGetSymbolAddress((void**)&h3lo, g_h3lo);
    cudaGetSymbolAddress((void**)&B1hi, g_B1hi);
    cudaGetSymbolAddress((void**)&B1lo, g_B1lo);
    cudaGetSymbolAddress((void**)&BQhi, g_BQhi);
    cudaGetSymbolAddress((void**)&BQlo, g_BQlo);
    cudaGetSymbolAddress((void**)&Bmehi, g_Bmehi);
    cudaGetSymbolAddress((void**)&Bmelo, g_Bmelo);
    cudaGetSymbolAddress((void**)&bme, g_bme);
    cudaGetSymbolAddress((void**)&B4hi, g_B4hi);
    cudaGetSymbolAddress((void**)&B4lo, g_B4lo);
    cudaGetSymbolAddress((void**)&zp, g_z);

    cudaFuncSetAttribute(mma_gemm<1, true>,  cudaFuncAttributeMaxDynamicSharedMemorySize, GEMM_SMEM);
    cudaFuncSetAttribute(mma_gemm<2, false>, cudaFuncAttributeMaxDynamicSharedMemorySize, GEMM_SMEM);
    cudaFuncSetAttribute(mma_gemm<4, false>, cudaFuncAttributeMaxDynamicSharedMemorySize, GEMM_SMEM);
    cudaFuncSetAttribute(mma_gemm<3, false>, cudaFuncAttributeMaxDynamicSharedMemorySize, GEMM_SMEM);

    // #1 x split (vectorized, exact)
    {
        long tot = (long)BATCH * (KP_X / 4);
        split_a4<<<(unsigned)((tot + 255) / 256), 256>>>(x, xhi, xlo);
    }
    // #2 W1 split
    split_wt<<<dim3((400 + 31) / 32, (KP_X + 31) / 32), 256>>>(W1, B1hi, B1lo, 784, 400, KP_X, 400);
    // #3 WQ split
    split_wt<<<dim3((2000 + 31) / 32, (KP_H + 31) / 32), 256>>>(WQ, BQhi, BQlo, 400, 2000, KP_H, 2000);
    // #4 fused mu|eigen weight + bias prep
    prep_me<<<(256 * KP_H + 255) / 256, 256>>>(Wmu, bmu, We, be, Bmehi, Bmelo, bme);
    // #5 h1 = relu(x@W1+b1) -> bf16 hi/lo
    mma_gemm<1, true><<<dim3(4, 256), 256, GEMM_SMEM>>>(
        xhi, xlo, B1hi, B1lo, b1, nullptr, nullptr, h1hi, h1lo, 400, KP_X, KP_H);
    // #6 Q = exp(h1@WQ+bQ)
    mma_gemm<2, false><<<dim3(16, 256), 256, GEMM_SMEM>>>(
        h1hi, h1lo, BQhi, BQlo, bQ, out_Q, nullptr, nullptr, nullptr, 2000, KP_H, 2000);
    // #7 W4 split
    split_wt<<<dim3((784 + 31) / 32, (KP_H + 31) / 32), 256>>>(W4, B4hi, B4lo, 400, 784, KP_H, 784);
    // #8 fused mu + eigen GEMM (N=256)
    mma_gemm<4, false><<<dim3(2, 256), 256, GEMM_SMEM>>>(
        h1hi, h1lo, Bmehi, Bmelo, bme, out_mu, out_eig, nullptr, nullptr, 256, KP_H, 100);
    // #9 softmax / idx / LU solve / z
    solve_kernel<<<BATCH / 8, 256>>>(Wa, ba, u, eps, h1hi, h1lo, out_Q, out_mu,
                                     out_eig, out_a, zp);
    // #10 h3 = relu(z@W3+b3) -> bf16 hi/lo
    h3_kernel<<<dim3(4, BATCH / 32), 128>>>(zp, W3, b3, h3hi, h3lo);
    // #11 recon = sigmoid(h3@W4+b4)
    mma_gemm<3, false><<<dim3(7, 256), 256, GEMM_SMEM>>>(
        h3hi, h3lo, B4hi, B4lo, b4, out_recon, nullptr, nullptr, nullptr, 784, KP_H, 784);
}

// round 8
// speedup vs baseline: 1.2233x; 1.0052x over previous
#include <cuda_runtime.h>
#include <cuda_bf16.h>
#include <math.h>
#include <stdint.h>

#define BATCH 32768
#define KP_X 784   // exact: 49 chunks of 16
#define KP_H 400   // exact: 25 chunks of 16

// ---------------- scratch (__device__ globals; no cudaMalloc allowed) ------
__device__ __align__(256) __nv_bfloat16 g_xhi[BATCH * KP_X];
__device__ __align__(256) __nv_bfloat16 g_xlo[BATCH * KP_X];
__device__ __align__(256) __nv_bfloat16 g_h1hi[BATCH * KP_H];
__device__ __align__(256) __nv_bfloat16 g_h1lo[BATCH * KP_H];
__device__ __align__(256) __nv_bfloat16 g_h3hi[BATCH * KP_H];
__device__ __align__(256) __nv_bfloat16 g_h3lo[BATCH * KP_H];
__device__ __align__(256) __nv_bfloat16 g_B1hi[400 * KP_X];
__device__ __align__(256) __nv_bfloat16 g_B1lo[400 * KP_X];
__device__ __align__(256) __nv_bfloat16 g_BQhi[2000 * KP_H];
__device__ __align__(256) __nv_bfloat16 g_BQlo[2000 * KP_H];
__device__ __align__(256) __nv_bfloat16 g_Bmehi[256 * KP_H];
__device__ __align__(256) __nv_bfloat16 g_Bmelo[256 * KP_H];
__device__ __align__(256) float g_bme[256];
__device__ __align__(256) __nv_bfloat16 g_B4hi[784 * KP_H];
__device__ __align__(256) __nv_bfloat16 g_B4lo[784 * KP_H];
__device__ float g_z[BATCH * 20];

// ---------------- helpers --------------------------------------------------
__device__ __forceinline__ uint32_t smem_u32(const void* p) {
    uint32_t a;
    asm("{ .reg .u64 t; cvta.to.shared.u64 t, %1; cvt.u32.u64 %0, t; }"
        : "=r"(a) : "l"(p));
    return a;
}
__device__ __forceinline__ void split2(float v, __nv_bfloat16& hi, __nv_bfloat16& lo) {
    hi = __float2bfloat16(v);
    lo = __float2bfloat16(v - __bfloat162float(hi));
}
template <int ACT>
__device__ __forceinline__ float act_apply(float v) {
    if (ACT == 1) return fmaxf(v, 0.f);
    if (ACT == 2) return expf(v);
    if (ACT == 3) return 1.f / (1.f + expf(-v));
    return v;
}

#define CP_ASYNC16(dst, src, sz) \
    asm volatile("cp.async.cg.shared.global [%0], [%1], 16, %2;" \
                 :: "r"(dst), "l"(src), "r"(sz) : "memory")
#define CP_COMMIT() asm volatile("cp.async.commit_group;" ::: "memory")
template <int NW>
__device__ __forceinline__ void cp_wait() {
    asm volatile("cp.async.wait_group %0;" :: "n"(NW) : "memory");
}

__device__ __forceinline__ void ldsm4(uint32_t* r, uint32_t addr) {
    asm volatile("ldmatrix.sync.aligned.m8n8.x4.shared.b16 {%0,%1,%2,%3}, [%4];"
                 : "=r"(r[0]), "=r"(r[1]), "=r"(r[2]), "=r"(r[3]) : "r"(addr));
}
__device__ __forceinline__ void mma16816(float* d, const uint32_t* a, const uint32_t* b) {
    asm volatile(
        "mma.sync.aligned.m16n8k16.row.col.f32.bf16.bf16.f32 "
        "{%0,%1,%2,%3}, {%4,%5,%6,%7}, {%8,%9}, {%0,%1,%2,%3};"
        : "+f"(d[0]), "+f"(d[1]), "+f"(d[2]), "+f"(d[3])
        : "r"(a[0]), "r"(a[1]), "r"(a[2]), "r"(a[3]), "r"(b[0]), "r"(b[1]));
}

// BK=16: row stride 32B (2 x 16B chunks); conflict-free swizzle
__device__ __forceinline__ uint32_t swoff16(int row, int ch) {
    return ((uint32_t)row << 5) + ((uint32_t)(ch ^ ((row >> 2) & 1)) << 4);
}

// ---------------- fused prep (ONE launch) ----------------------------------
// Block ranges: [0,25088) x-split | [25088,25413) W1 | [25413,26232) WQ
//               [26232,26632) me  | [26632,26957) W4
#define NB_X 25088
#define NB_W1 325   // 13 x 25 tiles
#define NB_WQ 819   // 63 x 13 tiles
#define NB_ME 400
#define NB_W4 325   // 25 x 13 tiles
#define NB_TOTAL (NB_X + NB_W1 + NB_WQ + NB_ME + NB_W4)

__device__ __forceinline__ void wt_tile(const float* __restrict__ W,
                                        __nv_bfloat16* __restrict__ hi,
                                        __nv_bfloat16* __restrict__ lo,
                                        int K, int N, int Kp, int Np,
                                        int tileN, int tileK, float* s /*32*33*/) {
    const int tx = threadIdx.x & 31, ty = threadIdx.x >> 5;
#pragma unroll
    for (int r = 0; r < 4; r++) {
        int kk = tileK + ty + r * 8, nn = tileN + tx;
        s[(ty + r * 8) * 33 + tx] = (kk < K && nn < N) ? W[(size_t)kk * N + nn] : 0.f;
    }
    __syncthreads();
#pragma unroll
    for (int r = 0; r < 4; r++) {
        int nn = tileN + ty + r * 8, kk = tileK + tx;
        if (nn < Np && kk < Kp) {
            __nv_bfloat16 h, l;
            split2(s[tx * 33 + ty + r * 8], h, l);
            hi[(size_t)nn * Kp + kk] = h;
            lo[(size_t)nn * Kp + kk] = l;
        }
    }
}

__global__ void __launch_bounds__(256)
mega_prep(const float* __restrict__ x, const float* __restrict__ W1,
          const float* __restrict__ WQ, const float* __restrict__ Wmu,
          const float* __restrict__ bmu, const float* __restrict__ We,
          const float* __restrict__ be, const float* __restrict__ W4,
          __nv_bfloat16* __restrict__ xhi, __nv_bfloat16* __restrict__ xlo,
          __nv_bfloat16* __restrict__ B1hi, __nv_bfloat16* __restrict__ B1lo,
          __nv_bfloat16* __restrict__ BQhi, __nv_bfloat16* __restrict__ BQlo,
          __nv_bfloat16* __restrict__ Bmehi, __nv_bfloat16* __restrict__ Bmelo,
          float* __restrict__ bme,
          __nv_bfloat16* __restrict__ B4hi, __nv_bfloat16* __restrict__ B4lo) {
    __shared__ float s[32 * 33];
    int b = blockIdx.x;
    if (b < NB_X) {
        // x split: float4-wide, exact
        const int per_row = KP_X / 4;  // 196
        long i = (long)b * 256 + threadIdx.x;
        if (i < (long)BATCH * per_row) {
            int k = (int)(i % per_row) * 4;
            long r = i / per_row;
            float4 v = *(const float4*)(x + r * KP_X + k);
            __nv_bfloat16 h[4], l[4];
            split2(v.x, h[0], l[0]);
            split2(v.y, h[1], l[1]);
            split2(v.z, h[2], l[2]);
            split2(v.w, h[3], l[3]);
            *(uint2*)(xhi + r * KP_X + k) = *(uint2*)h;
            *(uint2*)(xlo + r * KP_X + k) = *(uint2*)l;
        }
        return;
    }
    b -= NB_X;
    if (b < NB_W1) {
        wt_tile(W1, B1hi, B1lo, 784, 400, KP_X, 400, (b % 13) * 32, (b / 13) * 32, s);
        return;
    }
    b -= NB_W1;
    if (b < NB_WQ) {
        wt_tile(WQ, BQhi, BQlo, 400, 2000, KP_H, 2000, (b % 63) * 32, (b / 63) * 32, s);
        return;
    }
    b -= NB_WQ;
    if (b < NB_ME) {
        int i = b * 256 + threadIdx.x;
        if (i < 256) {
            bme[i] = (i < 100) ? bmu[i] : ((i >= 128 && i < 228) ? be[i - 128] : 0.f);
        }
        if (i < 256 * KP_H) {
            int n = i / KP_H, k = i % KP_H;
            float v = 0.f;
            if (n < 100) v = Wmu[(size_t)k * 100 + n];
            else if (n >= 128 && n < 228) v = We[(size_t)k * 100 + (n - 128)];
            __nv_bfloat16 h, l;
            split2(v, h, l);
            Bmehi[i] = h;
            Bmelo[i] = l;
        }
        return;
    }
    b -= NB_ME;
    wt_tile(W4, B4hi, B4lo, 400, 784, KP_H, 784, (b % 25) * 32, (b / 25) * 32, s);
}

// ---------------- 3-term bf16 split GEMM on mma.sync -----------------------
#define STAGES 4
#define STAGE_BYTES 16384
#define GEMM_SMEM (STAGES * STAGE_BYTES)

template <int ACT, bool SPLIT_OUT>
__global__ void __launch_bounds__(256, 2)
mma_gemm(const __nv_bfloat16* __restrict__ Ahi, const __nv_bfloat16* __restrict__ Alo,
         const __nv_bfloat16* __restrict__ Bhi, const __nv_bfloat16* __restrict__ Blo,
         const float* __restrict__ bias, float* __restrict__ C, float* __restrict__ C2,
         __nv_bfloat16* __restrict__ outHi, __nv_bfloat16* __restrict__ outLo,
         int N, int Kp, int ldOut) {
    extern __shared__ char smem[];
    const uint32_t sbase = smem_u32(smem);
    const int tid = threadIdx.x, wid = tid >> 5, lane = tid & 31;
    const int wm = wid >> 1, wn = wid & 1;
    const int rowBase = blockIdx.y * 128, colBase = blockIdx.x * 128;
    const int NC = Kp >> 4;

    float acc[2][8][4];
#pragma unroll
    for (int i = 0; i < 2; i++)
#pragma unroll
        for (int j = 0; j < 8; j++)
#pragma unroll
            for (int q = 0; q < 4; q++) acc[i][j][q] = 0.f;

    auto load_stage = [&](int c, int stg) {
        const int kBase = c << 4;
        const uint32_t sb = sbase + stg * STAGE_BYTES;
        const int row = tid >> 1, ch = tid & 1;
        const uint32_t o = swoff16(row, ch);
        const int arow = rowBase + row;
        int brow = colBase + row, bsz = 16;
        if (brow >= N) { brow = 0; bsz = 0; }
        const size_t aoff = (size_t)arow * Kp + kBase + ch * 8;
        const size_t boff = (size_t)brow * Kp + kBase + ch * 8;
        CP_ASYNC16(sb + o, Ahi + aoff, 16);
        CP_ASYNC16(sb + 4096 + o, Alo + aoff, 16);
        CP_ASYNC16(sb + 8192 + o, Bhi + boff, bsz);
        CP_ASYNC16(sb + 12288 + o, Blo + boff, bsz);
    };

    load_stage(0, 0);
    CP_COMMIT();
    load_stage(1, 1);
    CP_COMMIT();
    load_stage(2, 2);
    CP_COMMIT();

    for (int c = 0; c < NC; c++) {
        cp_wait<STAGES - 2>();
        __syncthreads();
        if (c + STAGES - 1 < NC) {
            load_stage(c + STAGES - 1, (c + STAGES - 1) % STAGES);
            CP_COMMIT();
        }
        const uint32_t sb = sbase + (c % STAGES) * STAGE_BYTES;

        uint32_t ahi[2][4], alo[2][4];
#pragma unroll
        for (int mi = 0; mi < 2; mi++) {
            int row = wm * 32 + mi * 16 + (lane & 15);
            int ch = lane >> 4;
            uint32_t o = swoff16(row, ch);
            ldsm4(ahi[mi], sb + o);
            ldsm4(alo[mi], sb + 4096 + o);
        }
#pragma unroll
        for (int bi = 0; bi < 4; bi++) {
            int row = wn * 64 + bi * 16 + (lane & 7) + ((lane >> 4) << 3);
            int ch = (lane >> 3) & 1;
            uint32_t o = swoff16(row, ch);
            uint32_t bhi[4], blo[4];
            ldsm4(bhi, sb + 8192 + o);
            ldsm4(blo, sb + 12288 + o);
            mma16816(acc[0][2 * bi],     ahi[0], bhi);
            mma16816(acc[0][2 * bi + 1], ahi[0], bhi + 2);
            mma16816(acc[1][2 * bi],     ahi[1], bhi);
            mma16816(acc[1][2 * bi + 1], ahi[1], bhi + 2);
            mma16816(acc[0][2 * bi],     alo[0], bhi);
            mma16816(acc[0][2 * bi + 1], alo[0], bhi + 2);
            mma16816(acc[1][2 * bi],     alo[1], bhi);
            mma16816(acc[1][2 * bi + 1], alo[1], bhi + 2);
            mma16816(acc[0][2 * bi],     ahi[0], blo);
            mma16816(acc[0][2 * bi + 1], ahi[0], blo + 2);
            mma16816(acc[1][2 * bi],     ahi[1], blo);
            mma16816(acc[1][2 * bi + 1], ahi[1], blo + 2);
        }
    }

    // ---------------- epilogue ----------------
#pragma unroll
    for (int mi = 0; mi < 2; mi++) {
#pragma unroll
        for (int ni = 0; ni < 8; ni++) {
            const float* a4 = acc[mi][ni];
            const int r0 = rowBase + wm * 32 + mi * 16 + (lane >> 2);
            const int col = colBase + wn * 64 + ni * 8 + ((lane & 3) << 1);
            float b0 = (col < N) ? bias[col] : 0.f;
            float b1 = (col + 1 < N) ? bias[col + 1] : 0.f;
#pragma unroll
            for (int h = 0; h < 2; h++) {
                const size_t row = (size_t)(r0 + h * 8);
                if (ACT == 4) {
                    float v0 = a4[2 * h + 0] + b0;
                    float v1 = a4[2 * h + 1] + b1;
                    if (col < 100) C[row * 100 + col] = v0;
                    else if (col >= 128 && col < 228) C2[row * 100 + col - 128] = expf(v0);
                    if (col + 1 < 100) C[row * 100 + col + 1] = v1;
                    else if (col + 1 >= 128 && col + 1 < 228) C2[row * 100 + col + 1 - 128] = expf(v1);
                    continue;
                }
                const float v0 = act_apply<ACT>(a4[2 * h + 0] + b0);
                const float v1 = act_apply<ACT>(a4[2 * h + 1] + b1);
                if (SPLIT_OUT) {
                    if (col < N) {
                        __nv_bfloat16 hh, ll;
                        split2(v0, hh, ll);
                        outHi[row * ldOut + col] = hh;
                        outLo[row * ldOut + col] = ll;
                        if (col + 1 < N) {
                            split2(v1, hh, ll);
                            outHi[row * ldOut + col + 1] = hh;
                            outLo[row * ldOut + col + 1] = ll;
                        }
                    }
                } else {
                    if (col < N) C[row * ldOut + col] = v0;
                    if (col + 1 < N) C[row * ldOut + col + 1] = v1;
                }
            }
        }
    }
}

// ---------------- per-row solve kernel ------------------------------------
__global__ void __launch_bounds__(256)
solve_kernel(const float* __restrict__ Wa, const float* __restrict__ ba,
             const float* __restrict__ u, const float* __restrict__ eps,
             const __nv_bfloat16* __restrict__ h1hi, const __nv_bfloat16* __restrict__ h1lo,
             const float* __restrict__ outQ, const float* __restrict__ outMu,
             const float* __restrict__ outEig, float* __restrict__ outA,
             float* __restrict__ z) {
    __shared__ float Qs[8][400];
    const unsigned FULL = 0xffffffffu;
    const int w = threadIdx.x >> 5, lane = threadIdx.x & 31;
    const int row = blockIdx.x * 8 + w;

    float s0 = 0, s1 = 0, s2 = 0, s3 = 0, s4 = 0;
    const __nv_bfloat16* hh = h1hi + (size_t)row * KP_H;
    const __nv_bfloat16* hl = h1lo + (size_t)row * KP_H;
    for (int k = lane; k < 400; k += 32) {
        float h = __bfloat162float(hh[k]) + __bfloat162float(hl[k]);
        const float* wk = Wa + k * 5;
        s0 = fmaf(h, wk[0], s0);
        s1 = fmaf(h, wk[1], s1);
        s2 = fmaf(h, wk[2], s2);
        s3 = fmaf(h, wk[3], s3);
        s4 = fmaf(h, wk[4], s4);
    }
#pragma unroll
    for (int off = 16; off; off >>= 1) {
        s0 += __shfl_xor_sync(FULL, s0, off);
        s1 += __shfl_xor_sync(FULL, s1, off);
        s2 += __shfl_xor_sync(FULL, s2, off);
        s3 += __shfl_xor_sync(FULL, s3, off);
        s4 += __shfl_xor_sync(FULL, s4, off);
    }
    s0 += ba[0]; s1 += ba[1]; s2 += ba[2]; s3 += ba[3]; s4 += ba[4];
    float mx = fmaxf(fmaxf(fmaxf(s0, s1), fmaxf(s2, s3)), s4);
    float e0 = expf(s0 - mx), e1 = expf(s1 - mx), e2 = expf(s2 - mx),
          e3 = expf(s3 - mx), e4 = expf(s4 - mx);
    float inv = 1.f / (e0 + e1 + e2 + e3 + e4);
    float av[5] = {e0 * inv, e1 * inv, e2 * inv, e3 * inv, e4 * inv};
    if (lane == 0) {
        float* ar = outA + (size_t)row * 5;
        ar[0] = av[0]; ar[1] = av[1]; ar[2] = av[2]; ar[3] = av[3]; ar[4] = av[4];
    }

    float uu = u[row];
    int idx = 0;
    bool found = false;
    float c = 0.f;
#pragma unroll
    for (int j = 0; j < 5; j++) {
        c += av[j];
        if (!found && uu < c) { idx = j; found = true; }
    }

    const float* Qr = outQ + (size_t)row * 2000 + idx * 400;
    for (int k = lane; k < 400; k += 32) Qs[w][k] = Qr[k];
    __syncwarp();

    float o[20], r[20];
    float rhs = 0.f, eig = 0.f, mui = 0.f;
    if (lane < 20) {
#pragma unroll
        for (int j = 0; j < 20; j++) o[j] = Qs[w][lane * 20 + j];
        rhs = eps[(size_t)row * 20 + lane];
        eig = outEig[(size_t)row * 100 + idx * 20 + lane];
        mui = outMu[(size_t)row * 100 + idx * 20 + lane];
    } else {
#pragma unroll
        for (int j = 0; j < 20; j++) o[j] = 0.f;
    }
#pragma unroll
    for (int j = 0; j < 20; j++) r[j] = o[j];

#pragma unroll
    for (int k = 0; k < 20; k++) {
        float key = (lane >= k && lane < 20) ? fabsf(r[k]) : -1.0f;
        int pi = lane;
#pragma unroll
        for (int off = 16; off; off >>= 1) {
            float ok = __shfl_xor_sync(FULL, key, off);
            int oi = __shfl_xor_sync(FULL, pi, off);
            if (ok > key || (ok == key && oi < pi)) { key = ok; pi = oi; }
        }
        if (pi != k) {
            int partner = (lane == k) ? pi : ((lane == pi) ? k : lane);
#pragma unroll
            for (int j = 0; j < 20; j++) r[j] = __shfl_sync(FULL, r[j], partner);
            rhs = __shfl_sync(FULL, rhs, partner);
        }
        float akk = __shfl_sync(FULL, r[k], k);
        float m = (lane > k && lane < 20) ? r[k] / akk : 0.0f;
        float rk = __shfl_sync(FULL, rhs, k);
        rhs = fmaf(-m, rk, rhs);
#pragma unroll
        for (int j = k + 1; j < 20; j++) {
            float akj = __shfl_sync(FULL, r[j], k);
            r[j] = fmaf(-m, akj, r[j]);
        }
    }

    float y = 0.f;
#pragma unroll
    for (int k = 19; k >= 0; k--) {
        float num = __shfl_sync(FULL, rhs, k);
        float akk = __shfl_sync(FULL, r[k], k);
        float yk = num / akk;
        if (lane == k) y = yk;
        if (lane < k) rhs = fmaf(-r[k], yk, rhs);
    }

    float wv = eig * y;
    float zv = mui;
#pragma unroll
    for (int j = 0; j < 20; j++) {
        float wj = __shfl_sync(FULL, wv, j);
        zv = fmaf(o[j], wj, zv);
    }
    if (lane < 20) z[(size_t)row * 20 + lane] = zv;
}

// ---------------- h3 = relu(z@W3+b3) -> bf16 hi/lo -------------------------
__global__ void __launch_bounds__(128)
h3_kernel(const float* __restrict__ z, const float* __restrict__ W3,
          const float* __restrict__ b3, __nv_bfloat16* __restrict__ h3hi,
          __nv_bfloat16* __restrict__ h3lo) {
    __shared__ float zs[32 * 20];
    const int col = blockIdx.x * 128 + threadIdx.x;
    const int row0 = blockIdx.y * 32;
    for (int i = threadIdx.x; i < 32 * 20; i += 128)
        zs[i] = z[(size_t)row0 * 20 + i];
    __syncthreads();

    if (col < 400) {
        float wcol[20];
#pragma unroll
        for (int k = 0; k < 20; k++) wcol[k] = W3[k * 400 + col];
        float bias = b3[col];
        for (int rr = 0; rr < 32; rr++) {
            float acc = bias;
#pragma unroll
            for (int k = 0; k < 20; k++)
                acc = fmaf(zs[rr * 20 + k], wcol[k], acc);
            float v = fmaxf(acc, 0.f);
            __nv_bfloat16 h, l;
            split2(v, h, l);
            h3hi[(size_t)(row0 + rr) * KP_H + col] = h;
            h3lo[(size_t)(row0 + rr) * KP_H + col] = l;
        }
    }
}

// ---------------- launch ---------------------------------------------------
extern "C" void kernel_launch(void* const* d_in, const int* in_sizes, int n_in,
                              void* d_out, int out_size) {
    const float* x   = (const float*)d_in[0];
    const float* u   = (const float*)d_in[1];
    const float* eps = (const float*)d_in[2];
    const float* W1  = (const float*)d_in[3];
    const float* b1  = (const float*)d_in[4];
    const float* Wmu = (const float*)d_in[5];
    const float* bmu = (const float*)d_in[6];
    const float* WQ  = (const float*)d_in[7];
    const float* bQ  = (const float*)d_in[8];
    const float* Wa  = (const float*)d_in[9];
    const float* ba  = (const float*)d_in[10];
    const float* We  = (const float*)d_in[11];
    const float* be  = (const float*)d_in[12];
    const float* W3  = (const float*)d_in[13];
    const float* b3  = (const float*)d_in[14];
    const float* W4  = (const float*)d_in[15];
    const float* b4  = (const float*)d_in[16];

    float* out = (float*)d_out;
    float* out_recon = out;
    float* out_mu    = out_recon + (size_t)BATCH * 784;
    float* out_Q     = out_mu    + (size_t)BATCH * 100;
    float* out_a     = out_Q     + (size_t)BATCH * 2000;
    float* out_eig   = out_a     + (size_t)BATCH * 5;

    __nv_bfloat16 *xhi, *xlo, *h1hi, *h1lo, *h3hi, *h3lo;
    __nv_bfloat16 *B1hi, *B1lo, *BQhi, *BQlo, *Bmehi, *Bmelo, *B4hi, *B4lo;
    float *zp, *bme;
    cudaGetSymbolAddress((void**)&xhi, g_xhi);
    cudaGetSymbolAddress((void**)&xlo, g_xlo);
    cudaGetSymbolAddress((void**)&h1hi, g_h1hi);
    cudaGetSymbolAddress((void**)&h1lo, g_h1lo);
    cudaGetSymbolAddress((void**)&h3hi, g_h3hi);
    cudaGetSymbolAddress((void**)&h3lo, g_h3lo);
    cudaGetSymbolAddress((void**)&B1hi, g_B1hi);
    cudaGetSymbolAddress((void**)&B1lo, g_B1lo);
    cudaGetSymbolAddress((void**)&BQhi, g_BQhi);
    cudaGetSymbolAddress((void**)&BQlo, g_BQlo);
    cudaGetSymbolAddress((void**)&Bmehi, g_Bmehi);
    cudaGetSymbolAddress((void**)&Bmelo, g_Bmelo);
    cudaGetSymbolAddress((void**)&bme, g_bme);
    cudaGetSymbolAddress((void**)&B4hi, g_B4hi);
    cudaGetSymbolAddress((void**)&B4lo, g_B4lo);
    cudaGetSymbolAddress((void**)&zp, g_z);

    cudaFuncSetAttribute(mma_gemm<1, true>,  cudaFuncAttributeMaxDynamicSharedMemorySize, GEMM_SMEM);
    cudaFuncSetAttribute(mma_gemm<2, false>, cudaFuncAttributeMaxDynamicSharedMemorySize, GEMM_SMEM);
    cudaFuncSetAttribute(mma_gemm<4, false>, cudaFuncAttributeMaxDynamicSharedMemorySize, GEMM_SMEM);
    cudaFuncSetAttribute(mma_gemm<3, false>, cudaFuncAttributeMaxDynamicSharedMemorySize, GEMM_SMEM);

    // #1 all prep in ONE launch
    mega_prep<<<NB_TOTAL, 256>>>(x, W1, WQ, Wmu, bmu, We, be, W4,
                                 xhi, xlo, B1hi, B1lo, BQhi, BQlo,
                                 Bmehi, Bmelo, bme, B4hi, B4lo);
    // #2 h1 = relu(x@W1+b1) -> bf16 hi/lo
    mma_gemm<1, true><<<dim3(4, 256), 256, GEMM_SMEM>>>(
        xhi, xlo, B1hi, B1lo, b1, nullptr, nullptr, h1hi, h1lo, 400, KP_X, KP_H);
    // #3 fused mu + eigen GEMM (N=256)
    mma_gemm<4, false><<<dim3(2, 256), 256, GEMM_SMEM>>>(
        h1hi, h1lo, Bmehi, Bmelo, bme, out_mu, out_eig, nullptr, nullptr, 256, KP_H, 100);
    // #4 Q = exp(h1@WQ+bQ)   <-- ncu's captured launch
    mma_gemm<2, false><<<dim3(16, 256), 256, GEMM_SMEM>>>(
        h1hi, h1lo, BQhi, BQlo, bQ, out_Q, nullptr, nullptr, nullptr, 2000, KP_H, 2000);
    // #5 softmax / idx / LU solve / z
    solve_kernel<<<BATCH / 8, 256>>>(Wa, ba, u, eps, h1hi, h1lo, out_Q, out_mu,
                                     out_eig, out_a, zp);
    // #6 h3 = relu(z@W3+b3) -> bf16 hi/lo
    h3_kernel<<<dim3(4, BATCH / 32), 128>>>(zp, W3, b3, h3hi, h3lo);
    // #7 recon = sigmoid(h3@W4+b4)
    mma_gemm<3, false><<<dim3(7, 256), 256, GEMM_SMEM>>>(
        h3hi, h3lo, B4hi, B4lo, b4, out_recon, nullptr, nullptr, nullptr, 784, KP_H, 784);
}

// round 9
// speedup vs baseline: 1.2651x; 1.0342x over previous
#include <cuda_runtime.h>
#include <cuda_bf16.h>
#include <math.h>
#include <stdint.h>

#define BATCH 32768
#define KP_X 784   // exact: 49 chunks of 16
#define KP_H 400   // exact: 25 chunks of 16
#define NQME 2304  // 2000 Q | pad 48 | 100 mu (@2048) | pad | 100 eig (@2176) | pad

// ---------------- scratch (__device__ globals; no cudaMalloc allowed) ------
__device__ __align__(256) __nv_bfloat16 g_xhi[BATCH * KP_X];
__device__ __align__(256) __nv_bfloat16 g_xlo[BATCH * KP_X];
__device__ __align__(256) __nv_bfloat16 g_h1hi[BATCH * KP_H];
__device__ __align__(256) __nv_bfloat16 g_h1lo[BATCH * KP_H];
__device__ __align__(256) __nv_bfloat16 g_h3hi[BATCH * KP_H];
__device__ __align__(256) __nv_bfloat16 g_h3lo[BATCH * KP_H];
__device__ __align__(256) __nv_bfloat16 g_B1hi[400 * KP_X];
__device__ __align__(256) __nv_bfloat16 g_B1lo[400 * KP_X];
__device__ __align__(256) __nv_bfloat16 g_BQMhi[NQME * KP_H];
__device__ __align__(256) __nv_bfloat16 g_BQMlo[NQME * KP_H];
__device__ __align__(256) float g_bqme[NQME];
__device__ __align__(256) __nv_bfloat16 g_B4hi[784 * KP_H];
__device__ __align__(256) __nv_bfloat16 g_B4lo[784 * KP_H];
__device__ float g_z[BATCH * 20];

// ---------------- helpers --------------------------------------------------
__device__ __forceinline__ uint32_t smem_u32(const void* p) {
    uint32_t a;
    asm("{ .reg .u64 t; cvta.to.shared.u64 t, %1; cvt.u32.u64 %0, t; }"
        : "=r"(a) : "l"(p));
    return a;
}
__device__ __forceinline__ void split2(float v, __nv_bfloat16& hi, __nv_bfloat16& lo) {
    hi = __float2bfloat16(v);
    lo = __float2bfloat16(v - __bfloat162float(hi));
}
template <int ACT>
__device__ __forceinline__ float act_apply(float v) {
    if (ACT == 1) return fmaxf(v, 0.f);
    if (ACT == 2) return expf(v);
    if (ACT == 3) return 1.f / (1.f + expf(-v));
    return v;
}

#define CP_ASYNC16(dst, src, sz) \
    asm volatile("cp.async.cg.shared.global [%0], [%1], 16, %2;" \
                 :: "r"(dst), "l"(src), "r"(sz) : "memory")
#define CP_COMMIT() asm volatile("cp.async.commit_group;" ::: "memory")
template <int NW>
__device__ __forceinline__ void cp_wait() {
    asm volatile("cp.async.wait_group %0;" :: "n"(NW) : "memory");
}

__device__ __forceinline__ void ldsm4(uint32_t* r, uint32_t addr) {
    asm volatile("ldmatrix.sync.aligned.m8n8.x4.shared.b16 {%0,%1,%2,%3}, [%4];"
                 : "=r"(r[0]), "=r"(r[1]), "=r"(r[2]), "=r"(r[3]) : "r"(addr));
}
__device__ __forceinline__ void mma16816(float* d, const uint32_t* a, const uint32_t* b) {
    asm volatile(
        "mma.sync.aligned.m16n8k16.row.col.f32.bf16.bf16.f32 "
        "{%0,%1,%2,%3}, {%4,%5,%6,%7}, {%8,%9}, {%0,%1,%2,%3};"
        : "+f"(d[0]), "+f"(d[1]), "+f"(d[2]), "+f"(d[3])
        : "r"(a[0]), "r"(a[1]), "r"(a[2]), "r"(a[3]), "r"(b[0]), "r"(b[1]));
}
__device__ __forceinline__ uint32_t redux_max(uint32_t v) {
    uint32_t m;
    asm("redux.sync.max.u32 %0, %1, 0xffffffff;" : "=r"(m) : "r"(v));
    return m;
}

// BK=16: row stride 32B (2 x 16B chunks); conflict-free swizzle
__device__ __forceinline__ uint32_t swoff16(int row, int ch) {
    return ((uint32_t)row << 5) + ((uint32_t)(ch ^ ((row >> 2) & 1)) << 4);
}

// ---------------- fused prep (ONE launch) ----------------------------------
#define NB_X 25088
#define NB_W1 325          // 13 n-tiles x 25 k-tiles
#define NB_QME (72 * 13)   // 936
#define NB_BIAS 9
#define NB_W4 325          // 25 n-tiles x 13 k-tiles
#define NB_TOTAL (NB_X + NB_W1 + NB_QME + NB_BIAS + NB_W4)

__device__ __forceinline__ void wt_tile(const float* __restrict__ W,
                                        __nv_bfloat16* __restrict__ hi,
                                        __nv_bfloat16* __restrict__ lo,
                                        int K, int N, int Kp, int Np,
                                        int tileN, int tileK, float* s) {
    const int tx = threadIdx.x & 31, ty = threadIdx.x >> 5;
#pragma unroll
    for (int r = 0; r < 4; r++) {
        int kk = tileK + ty + r * 8, nn = tileN + tx;
        s[(ty + r * 8) * 33 + tx] = (kk < K && nn < N) ? W[(size_t)kk * N + nn] : 0.f;
    }
    __syncthreads();
#pragma unroll
    for (int r = 0; r < 4; r++) {
        int nn = tileN + ty + r * 8, kk = tileK + tx;
        if (nn < Np && kk < Kp) {
            __nv_bfloat16 h, l;
            split2(s[tx * 33 + ty + r * 8], h, l);
            hi[(size_t)nn * Kp + kk] = h;
            lo[(size_t)nn * Kp + kk] = l;
        }
    }
}

__device__ __forceinline__ float qme_src(const float* WQ, const float* Wmu,
                                         const float* We, int k, int n) {
    if (k >= 400) return 0.f;
    if (n < 2000) return WQ[(size_t)k * 2000 + n];
    if (n >= 2048 && n < 2148) return Wmu[(size_t)k * 100 + (n - 2048)];
    if (n >= 2176 && n < 2276) return We[(size_t)k * 100 + (n - 2176)];
    return 0.f;
}

__global__ void __launch_bounds__(256)
mega_prep(const float* __restrict__ x, const float* __restrict__ W1,
          const float* __restrict__ WQ, const float* __restrict__ bQ,
          const float* __restrict__ Wmu, const float* __restrict__ bmu,
          const float* __restrict__ We, const float* __restrict__ be,
          const float* __restrict__ W4,
          __nv_bfloat16* __restrict__ xhi, __nv_bfloat16* __restrict__ xlo,
          __nv_bfloat16* __restrict__ B1hi, __nv_bfloat16* __restrict__ B1lo,
          __nv_bfloat16* __restrict__ BQMhi, __nv_bfloat16* __restrict__ BQMlo,
          float* __restrict__ bqme,
          __nv_bfloat16* __restrict__ B4hi, __nv_bfloat16* __restrict__ B4lo) {
    __shared__ float s[32 * 33];
    int b = blockIdx.x;
    if (b < NB_X) {
        const int per_row = KP_X / 4;  // 196
        long i = (long)b * 256 + threadIdx.x;
        if (i < (long)BATCH * per_row) {
            int k = (int)(i % per_row) * 4;
            long r = i / per_row;
            float4 v = *(const float4*)(x + r * KP_X + k);
            __nv_bfloat16 h[4], l[4];
            split2(v.x, h[0], l[0]);
            split2(v.y, h[1], l[1]);
            split2(v.z, h[2], l[2]);
            split2(v.w, h[3], l[3]);
            *(uint2*)(xhi + r * KP_X + k) = *(uint2*)h;
            *(uint2*)(xlo + r * KP_X + k) = *(uint2*)l;
        }
        return;
    }
    b -= NB_X;
    if (b < NB_W1) {
        wt_tile(W1, B1hi, B1lo, 784, 400, KP_X, 400, (b % 13) * 32, (b / 13) * 32, s);
        return;
    }
    b -= NB_W1;
    if (b < NB_QME) {
        const int tileN = (b % 72) * 32, tileK = (b / 72) * 32;
        const int tx = threadIdx.x & 31, ty = threadIdx.x >> 5;
#pragma unroll
        for (int r = 0; r < 4; r++) {
            int kk = tileK + ty + r * 8, nn = tileN + tx;
            s[(ty + r * 8) * 33 + tx] = qme_src(WQ, Wmu, We, kk, nn);
        }
        __syncthreads();
#pragma unroll
        for (int r = 0; r < 4; r++) {
            int nn = tileN + ty + r * 8, kk = tileK + tx;
            if (kk < KP_H) {
                __nv_bfloat16 h, l;
                split2(s[tx * 33 + ty + r * 8], h, l);
                BQMhi[(size_t)nn * KP_H + kk] = h;
                BQMlo[(size_t)nn * KP_H + kk] = l;
            }
        }
        return;
    }
    b -= NB_QME;
    if (b < NB_BIAS) {
        int i = b * 256 + threadIdx.x;
        if (i < NQME) {
            float v = 0.f;
            if (i < 2000) v = bQ[i];
            else if (i >= 2048 && i < 2148) v = bmu[i - 2048];
            else if (i >= 2176 && i < 2276) v = be[i - 2176];
            bqme[i] = v;
        }
        return;
    }
    b -= NB_BIAS;
    wt_tile(W4, B4hi, B4lo, 400, 784, KP_H, 784, (b % 25) * 32, (b / 25) * 32, s);
}

// ---------------- 3-term bf16 split GEMM on mma.sync -----------------------
#define STAGES 4
#define STAGE_BYTES 16384
#define GEMM_SMEM (STAGES * STAGE_BYTES)

__device__ __forceinline__ void qme_store(float* __restrict__ Q, float* __restrict__ mu,
                                          float* __restrict__ eig, size_t row, int col,
                                          float v) {
    if (col < 2000) Q[row * 2000 + col] = expf(v);
    else if (col >= 2048 && col < 2148) mu[row * 100 + (col - 2048)] = v;
    else if (col >= 2176 && col < 2276) eig[row * 100 + (col - 2176)] = expf(v);
}

template <int ACT, bool SPLIT_OUT>
__global__ void __launch_bounds__(256, 2)
mma_gemm(const __nv_bfloat16* __restrict__ Ahi, const __nv_bfloat16* __restrict__ Alo,
         const __nv_bfloat16* __restrict__ Bhi, const __nv_bfloat16* __restrict__ Blo,
         const float* __restrict__ bias, float* __restrict__ C, float* __restrict__ C2,
         float* __restrict__ C3,
         __nv_bfloat16* __restrict__ outHi, __nv_bfloat16* __restrict__ outLo,
         int N, int Kp, int ldOut) {
    extern __shared__ char smem[];
    const uint32_t sbase = smem_u32(smem);
    const int tid = threadIdx.x, wid = tid >> 5, lane = tid & 31;
    const int wm = wid >> 1, wn = wid & 1;
    const int rowBase = blockIdx.y * 128, colBase = blockIdx.x * 128;
    const int NC = Kp >> 4;

    float acc[2][8][4];
#pragma unroll
    for (int i = 0; i < 2; i++)
#pragma unroll
        for (int j = 0; j < 8; j++)
#pragma unroll
            for (int q = 0; q < 4; q++) acc[i][j][q] = 0.f;

    auto load_stage = [&](int c, int stg) {
        const int kBase = c << 4;
        const uint32_t sb = sbase + stg * STAGE_BYTES;
        const int row = tid >> 1, ch = tid & 1;
        const uint32_t o = swoff16(row, ch);
        const int arow = rowBase + row;
        int brow = colBase + row, bsz = 16;
        if (brow >= N) { brow = 0; bsz = 0; }
        const size_t aoff = (size_t)arow * Kp + kBase + ch * 8;
        const size_t boff = (size_t)brow * Kp + kBase + ch * 8;
        CP_ASYNC16(sb + o, Ahi + aoff, 16);
        CP_ASYNC16(sb + 4096 + o, Alo + aoff, 16);
        CP_ASYNC16(sb + 8192 + o, Bhi + boff, bsz);
        CP_ASYNC16(sb + 12288 + o, Blo + boff, bsz);
    };

    load_stage(0, 0);
    CP_COMMIT();
    load_stage(1, 1);
    CP_COMMIT();
    load_stage(2, 2);
    CP_COMMIT();

    for (int c = 0; c < NC; c++) {
        cp_wait<STAGES - 2>();
        __syncthreads();
        if (c + STAGES - 1 < NC) {
            load_stage(c + STAGES - 1, (c + STAGES - 1) % STAGES);
            CP_COMMIT();
        }
        const uint32_t sb = sbase + (c % STAGES) * STAGE_BYTES;

        uint32_t ahi[2][4], alo[2][4];
#pragma unroll
        for (int mi = 0; mi < 2; mi++) {
            int row = wm * 32 + mi * 16 + (lane & 15);
            int ch = lane >> 4;
            uint32_t o = swoff16(row, ch);
            ldsm4(ahi[mi], sb + o);
            ldsm4(alo[mi], sb + 4096 + o);
        }
#pragma unroll
        for (int bi = 0; bi < 4; bi++) {
            int row = wn * 64 + bi * 16 + (lane & 7) + ((lane >> 4) << 3);
            int ch = (lane >> 3) & 1;
            uint32_t o = swoff16(row, ch);
            uint32_t bhi[4], blo[4];
            ldsm4(bhi, sb + 8192 + o);
            ldsm4(blo, sb + 12288 + o);
            mma16816(acc[0][2 * bi],     ahi[0], bhi);
            mma16816(acc[0][2 * bi + 1], ahi[0], bhi + 2);
            mma16816(acc[1][2 * bi],     ahi[1], bhi);
            mma16816(acc[1][2 * bi + 1], ahi[1], bhi + 2);
            mma16816(acc[0][2 * bi],     alo[0], bhi);
            mma16816(acc[0][2 * bi + 1], alo[0], bhi + 2);
            mma16816(acc[1][2 * bi],     alo[1], bhi);
            mma16816(acc[1][2 * bi + 1], alo[1], bhi + 2);
            mma16816(acc[0][2 * bi],     ahi[0], blo);
            mma16816(acc[0][2 * bi + 1], ahi[0], blo + 2);
            mma16816(acc[1][2 * bi],     ahi[1], blo);
            mma16816(acc[1][2 * bi + 1], ahi[1], blo + 2);
        }
    }

    // ---------------- epilogue ----------------
#pragma unroll
    for (int mi = 0; mi < 2; mi++) {
#pragma unroll
        for (int ni = 0; ni < 8; ni++) {
            const float* a4 = acc[mi][ni];
            const int r0 = rowBase + wm * 32 + mi * 16 + (lane >> 2);
            const int col = colBase + wn * 64 + ni * 8 + ((lane & 3) << 1);
            float b0 = (col < N) ? bias[col] : 0.f;
            float b1 = (col + 1 < N) ? bias[col + 1] : 0.f;
#pragma unroll
            for (int h = 0; h < 2; h++) {
                const size_t row = (size_t)(r0 + h * 8);
                if (ACT == 5) {  // fused Q | mu | eigen
                    qme_store(C, C2, C3, row, col, a4[2 * h + 0] + b0);
                    qme_store(C, C2, C3, row, col + 1, a4[2 * h + 1] + b1);
                    continue;
                }
                const float v0 = act_apply<ACT>(a4[2 * h + 0] + b0);
                const float v1 = act_apply<ACT>(a4[2 * h + 1] + b1);
                if (SPLIT_OUT) {
                    if (col < N) {
                        __nv_bfloat16 hh, ll;
                        split2(v0, hh, ll);
                        outHi[row * ldOut + col] = hh;
                        outLo[row * ldOut + col] = ll;
                        if (col + 1 < N) {
                            split2(v1, hh, ll);
                            outHi[row * ldOut + col + 1] = hh;
                            outLo[row * ldOut + col + 1] = ll;
                        }
                    }
                } else {
                    if (col < N) C[row * ldOut + col] = v0;
                    if (col + 1 < N) C[row * ldOut + col + 1] = v1;
                }
            }
        }
    }
}

// ---------------- per-row solve kernel (no-swap pivoted LU) ----------------
__global__ void __launch_bounds__(256)
solve_kernel(const float* __restrict__ Wa, const float* __restrict__ ba,
             const float* __restrict__ u, const float* __restrict__ eps,
             const __nv_bfloat16* __restrict__ h1hi, const __nv_bfloat16* __restrict__ h1lo,
             const float* __restrict__ outQ, const float* __restrict__ outMu,
             const float* __restrict__ outEig, float* __restrict__ outA,
             float* __restrict__ z) {
    __shared__ float Qs[8][400];
    __shared__ float sWa[2000];
    const unsigned FULL = 0xffffffffu;
    const int w = threadIdx.x >> 5, lane = threadIdx.x & 31;
    const int row = blockIdx.x * 8 + w;

    for (int i = threadIdx.x; i < 2000; i += 256) sWa[i] = Wa[i];
    __syncthreads();

    // --- a logits ---
    float s0 = 0, s1 = 0, s2 = 0, s3 = 0, s4 = 0;
    const __nv_bfloat16* hh = h1hi + (size_t)row * KP_H;
    const __nv_bfloat16* hl = h1lo + (size_t)row * KP_H;
    for (int k = lane; k < 400; k += 32) {
        float h = __bfloat162float(hh[k]) + __bfloat162float(hl[k]);
        const float* wk = sWa + k * 5;
        s0 = fmaf(h, wk[0], s0);
        s1 = fmaf(h, wk[1], s1);
        s2 = fmaf(h, wk[2], s2);
        s3 = fmaf(h, wk[3], s3);
        s4 = fmaf(h, wk[4], s4);
    }
#pragma unroll
    for (int off = 16; off; off >>= 1) {
        s0 += __shfl_xor_sync(FULL, s0, off);
        s1 += __shfl_xor_sync(FULL, s1, off);
        s2 += __shfl_xor_sync(FULL, s2, off);
        s3 += __shfl_xor_sync(FULL, s3, off);
        s4 += __shfl_xor_sync(FULL, s4, off);
    }
    s0 += ba[0]; s1 += ba[1]; s2 += ba[2]; s3 += ba[3]; s4 += ba[4];
    float mx = fmaxf(fmaxf(fmaxf(s0, s1), fmaxf(s2, s3)), s4);
    float e0 = expf(s0 - mx), e1 = expf(s1 - mx), e2 = expf(s2 - mx),
          e3 = expf(s3 - mx), e4 = expf(s4 - mx);
    float inv = 1.f / (e0 + e1 + e2 + e3 + e4);
    float av[5] = {e0 * inv, e1 * inv, e2 * inv, e3 * inv, e4 * inv};
    if (lane == 0) {
        float* ar = outA + (size_t)row * 5;
        ar[0] = av[0]; ar[1] = av[1]; ar[2] = av[2]; ar[3] = av[3]; ar[4] = av[4];
    }

    float uu = u[row];
    int idx = 0;
    bool found = false;
    float c = 0.f;
#pragma unroll
    for (int j = 0; j < 5; j++) {
        c += av[j];
        if (!found && uu < c) { idx = j; found = true; }
    }

    const float* Qr = outQ + (size_t)row * 2000 + idx * 400;
    for (int k = lane; k < 400; k += 32) Qs[w][k] = Qr[k];
    __syncwarp();

    float o[20], r[20];
    float rhs = 0.f, eig = 0.f, mui = 0.f;
    if (lane < 20) {
#pragma unroll
        for (int j = 0; j < 20; j++) o[j] = Qs[w][lane * 20 + j];
        rhs = eps[(size_t)row * 20 + lane];
        eig = outEig[(size_t)row * 100 + idx * 20 + lane];
        mui = outMu[(size_t)row * 100 + idx * 20 + lane];
    } else {
#pragma unroll
        for (int j = 0; j < 20; j++) o[j] = 0.f;
    }
#pragma unroll
    for (int j = 0; j < 20; j++) r[j] = o[j];

    // --- pivoted LU without row swaps: pivot stays in its lane ---
    unsigned done = 0;
    int p[20];
#pragma unroll
    for (int k = 0; k < 20; k++) {
        bool active = (lane < 20) && !(done & (1u << lane));
        uint32_t key = active ? __float_as_uint(fabsf(r[k])) : 0u;
        uint32_t m = redux_max(key);
        unsigned msk = __ballot_sync(FULL, active && key == m);
        int pi = __ffs(msk) - 1;
        p[k] = pi;
        done |= (1u << pi);
        float akk = __shfl_sync(FULL, r[k], pi);
        float prhs = __shfl_sync(FULL, rhs, pi);
        bool elim = (lane < 20) && !(done & (1u << lane));
        float mlt = elim ? r[k] / akk : 0.f;
        rhs = fmaf(-mlt, prhs, rhs);
#pragma unroll
        for (int j = k + 1; j < 20; j++) {
            float pj = __shfl_sync(FULL, r[j], pi);
            r[j] = fmaf(-mlt, pj, r[j]);
        }
    }

    // --- back substitution in pivot order ---
    float y = 0.f;
#pragma unroll
    for (int k = 19; k >= 0; k--) {
        int pk = p[k];
        float num = __shfl_sync(FULL, rhs, pk);
        float akk = __shfl_sync(FULL, r[k], pk);
        float yk = num / akk;
        if (lane == k) y = yk;
        rhs = fmaf(-r[k], yk, rhs);
    }

    // --- z = Q (eigen .* y) + mu ---
    float wv = eig * y;
    float zv = mui;
#pragma unroll
    for (int j = 0; j < 20; j++) {
        float wj = __shfl_sync(FULL, wv, j);
        zv = fmaf(o[j], wj, zv);
    }
    if (lane < 20) z[(size_t)row * 20 + lane] = zv;
}

// ---------------- h3 = relu(z@W3+b3) -> bf16 hi/lo -------------------------
__global__ void __launch_bounds__(128)
h3_kernel(const float* __restrict__ z, const float* __restrict__ W3,
          const float* __restrict__ b3, __nv_bfloat16* __restrict__ h3hi,
          __nv_bfloat16* __restrict__ h3lo) {
    __shared__ float zs[32 * 20];
    const int col = blockIdx.x * 128 + threadIdx.x;
    const int row0 = blockIdx.y * 32;
    for (int i = threadIdx.x; i < 32 * 20; i += 128)
        zs[i] = z[(size_t)row0 * 20 + i];
    __syncthreads();

    if (col < 400) {
        float wcol[20];
#pragma unroll
        for (int k = 0; k < 20; k++) wcol[k] = W3[k * 400 + col];
        float bias = b3[col];
        for (int rr = 0; rr < 32; rr++) {
            float acc = bias;
#pragma unroll
            for (int k = 0; k < 20; k++)
                acc = fmaf(zs[rr * 20 + k], wcol[k], acc);
            float v = fmaxf(acc, 0.f);
            __nv_bfloat16 h, l;
            split2(v, h, l);
            h3hi[(size_t)(row0 + rr) * KP_H + col] = h;
            h3lo[(size_t)(row0 + rr) * KP_H + col] = l;
        }
    }
}

// ---------------- launch ---------------------------------------------------
extern "C" void kernel_launch(void* const* d_in, const int* in_sizes, int n_in,
                              void* d_out, int out_size) {
    const float* x   = (const float*)d_in[0];
    const float* u   = (const float*)d_in[1];
    const float* eps = (const float*)d_in[2];
    const float* W1  = (const float*)d_in[3];
    const float* b1  = (const float*)d_in[4];
    const float* Wmu = (const float*)d_in[5];
    const float* bmu = (const float*)d_in[6];
    const float* WQ  = (const float*)d_in[7];
    const float* bQ  = (const float*)d_in[8];
    const float* Wa  = (const float*)d_in[9];
    const float* ba  = (const float*)d_in[10];
    const float* We  = (const float*)d_in[11];
    const float* be  = (const float*)d_in[12];
    const float* W3  = (const float*)d_in[13];
    const float* b3  = (const float*)d_in[14];
    const float* W4  = (const float*)d_in[15];
    const float* b4  = (const float*)d_in[16];

    float* out = (float*)d_out;
    float* out_recon = out;
    float* out_mu    = out_recon + (size_t)BATCH * 784;
    float* out_Q     = out_mu    + (size_t)BATCH * 100;
    float* out_a     = out_Q     + (size_t)BATCH * 2000;
    float* out_eig   = out_a     + (size_t)BATCH * 5;

    __nv_bfloat16 *xhi, *xlo, *h1hi, *h1lo, *h3hi, *h3lo;
    __nv_bfloat16 *B1hi, *B1lo, *BQMhi, *BQMlo, *B4hi, *B4lo;
    float *zp, *bqme;
    cudaGetSymbolAddress((void**)&xhi, g_xhi);
    cudaGetSymbolAddress((void**)&xlo, g_xlo);
    cudaGetSymbolAddress((void**)&h1hi, g_h1hi);
    cudaGetSymbolAddress((void**)&h1lo, g_h1lo);
    cudaGetSymbolAddress((void**)&h3hi, g_h3hi);
    cudaGetSymbolAddress((void**)&h3lo, g_h3lo);
    cudaGetSymbolAddress((void**)&B1hi, g_B1hi);
    cudaGetSymbolAddress((void**)&B1lo, g_B1lo);
    cudaGetSymbolAddress((void**)&BQMhi, g_BQMhi);
    cudaGetSymbolAddress((void**)&BQMlo, g_BQMlo);
    cudaGetSymbolAddress((void**)&bqme, g_bqme);
    cudaGetSymbolAddress((void**)&B4hi, g_B4hi);
    cudaGetSymbolAddress((void**)&B4lo, g_B4lo);
    cudaGetSymbolAddress((void**)&zp, g_z);

    cudaFuncSetAttribute(mma_gemm<1, true>,  cudaFuncAttributeMaxDynamicSharedMemorySize, GEMM_SMEM);
    cudaFuncSetAttribute(mma_gemm<5, false>, cudaFuncAttributeMaxDynamicSharedMemorySize, GEMM_SMEM);
    cudaFuncSetAttribute(mma_gemm<3, false>, cudaFuncAttributeMaxDynamicSharedMemorySize, GEMM_SMEM);

    // #1 all prep in ONE launch
    mega_prep<<<NB_TOTAL, 256>>>(x, W1, WQ, bQ, Wmu, bmu, We, be, W4,
                                 xhi, xlo, B1hi, B1lo, BQMhi, BQMlo, bqme,
                                 B4hi, B4lo);
    // #2 h1 = relu(x@W1+b1) -> bf16 hi/lo
    mma_gemm<1, true><<<dim3(4, 256), 256, GEMM_SMEM>>>(
        xhi, xlo, B1hi, B1lo, b1, nullptr, nullptr, nullptr, h1hi, h1lo, 400, KP_X, KP_H);
    // #3 fused Q | mu | eigen GEMM (N=2304)
    mma_gemm<5, false><<<dim3(18, 256), 256, GEMM_SMEM>>>(
        h1hi, h1lo, BQMhi, BQMlo, bqme, out_Q, out_mu, out_eig, nullptr, nullptr,
        NQME, KP_H, 0);
    // #4 softmax / idx / LU solve / z   <-- profiled launch
    solve_kernel<<<BATCH / 8, 256>>>(Wa, ba, u, eps, h1hi, h1lo, out_Q, out_mu,
                                     out_eig, out_a, zp);
    // #5 h3 = relu(z@W3+b3) -> bf16 hi/lo
    h3_kernel<<<dim3(4, BATCH / 32), 128>>>(zp, W3, b3, h3hi, h3lo);
    // #6 recon = sigmoid(h3@W4+b4)
    mma_gemm<3, false><<<dim3(7, 256), 256, GEMM_SMEM>>>(
        h3hi, h3lo, B4hi, B4lo, b4, out_recon, nullptr, nullptr, nullptr, nullptr,
        784, KP_H, 784);
}